// round 5
// baseline (speedup 1.0000x reference)
#include <cuda_runtime.h>
#include <math.h>
#include <stdint.h>

// Problem constants
constexpr int B  = 2;
constexpr int L  = 2048;
constexpr int D  = 1024;
constexpr int H  = 16;
constexpr int DH = 64;
constexpr int BL = B * L;          // 4096 tokens
constexpr float EPS   = 1e-5f;
constexpr float LOG_ROPE_BASE = 9.210340371976184f; // ln(10000)

// ---------------------------------------------------------------------------
// Scratch
// ---------------------------------------------------------------------------
__device__ float g_h[BL * D];            // post-LN hidden
__device__ float g_qkv[BL * 3 * D];      // qkv projection
__device__ float g_q[BL * D];            // q  [B,H,L,DH], tf32-rounded
__device__ float g_k[BL * D];            // k  [B,H,L,DH], tf32-rounded
__device__ float g_v[BL * D];            // v  [B,H,L,DH], tf32-rounded
__device__ float g_ctx[BL * D];          // attention output [B,L,H*DH]

// ---------------------------------------------------------------------------
// tf32 / mma / cp.async helpers
// ---------------------------------------------------------------------------
__device__ __forceinline__ float tf32r(float f) {
    uint32_t u; asm("cvt.rna.tf32.f32 %0, %1;" : "=r"(u) : "f"(f));
    return __uint_as_float(u);
}

__device__ __forceinline__ void mma8(float* c, const uint32_t* a, const uint32_t* b) {
    asm volatile(
        "mma.sync.aligned.m16n8k8.row.col.f32.tf32.tf32.f32 "
        "{%0,%1,%2,%3},{%4,%5,%6,%7},{%8,%9},{%0,%1,%2,%3};"
        : "+f"(c[0]), "+f"(c[1]), "+f"(c[2]), "+f"(c[3])
        : "r"(a[0]), "r"(a[1]), "r"(a[2]), "r"(a[3]), "r"(b[0]), "r"(b[1]));
}

__device__ __forceinline__ void cp_async16(uint32_t dst, const void* src) {
    asm volatile("cp.async.cg.shared.global [%0], [%1], 16;" :: "r"(dst), "l"(src));
}

// ---------------------------------------------------------------------------
// Block reduction (256 threads)
// ---------------------------------------------------------------------------
__device__ __forceinline__ float block_reduce_sum_256(float v, float* sbuf) {
    int tid = threadIdx.x;
    #pragma unroll
    for (int o = 16; o > 0; o >>= 1) v += __shfl_xor_sync(0xffffffffu, v, o);
    if ((tid & 31) == 0) sbuf[tid >> 5] = v;
    __syncthreads();
    if (tid < 8) {
        float w = sbuf[tid];
        #pragma unroll
        for (int o = 4; o > 0; o >>= 1) w += __shfl_xor_sync(0xffu, w, o);
        if (tid == 0) sbuf[0] = w;
    }
    __syncthreads();
    float r = sbuf[0];
    __syncthreads();
    return r;
}

// ---------------------------------------------------------------------------
// Kernel 1: LayerNorm over D=1024, one block (256 thr) per token.
// ---------------------------------------------------------------------------
__global__ void __launch_bounds__(256) ln_kernel(
    const float* __restrict__ x,
    const float* __restrict__ w,
    const float* __restrict__ bias)
{
    __shared__ float sbuf[8];
    const int t   = blockIdx.x;
    const int tid = threadIdx.x;

    const float4 xv = *(const float4*)(x + (size_t)t * D + 4 * tid);
    float s  = xv.x + xv.y + xv.z + xv.w;
    float ss = fmaf(xv.x, xv.x, fmaf(xv.y, xv.y, fmaf(xv.z, xv.z, xv.w * xv.w)));
    s  = block_reduce_sum_256(s,  sbuf);
    ss = block_reduce_sum_256(ss, sbuf);

    const float mu = s * (1.0f / D);
    const float rs = rsqrtf(ss * (1.0f / D) - mu * mu + EPS);

    const float4 wv = *(const float4*)(w    + 4 * tid);
    const float4 bv = *(const float4*)(bias + 4 * tid);
    float4 ov;
    ov.x = (xv.x - mu) * rs * wv.x + bv.x;
    ov.y = (xv.y - mu) * rs * wv.y + bv.y;
    ov.z = (xv.z - mu) * rs * wv.z + bv.z;
    ov.w = (xv.w - mu) * rs * wv.w + bv.w;
    *(float4*)(g_h + (size_t)t * D + 4 * tid) = ov;
}

// ---------------------------------------------------------------------------
// Kernel 2/5: tf32 tensor-core GEMM-NT (unchanged from R3)
// ---------------------------------------------------------------------------
constexpr int GSK = 20;

__global__ void __launch_bounds__(256) gemm_nt_tf32(
    const float* __restrict__ A,
    const float* __restrict__ Bm,
    float* __restrict__ C,
    int M, int N, int K)
{
    __shared__ float As[128][GSK];
    __shared__ float Bs[128][GSK];

    const int tid  = threadIdx.x;
    const int lane = tid & 31;
    const int g    = lane >> 2;
    const int tg   = lane & 3;
    const int wid  = tid >> 5;
    const int wm   = wid >> 2;
    const int wn   = wid & 3;
    const int m0   = blockIdx.y * 128;
    const int n0   = blockIdx.x * 128;

    const int lr = tid >> 2;
    const int lc = (tid & 3) * 4;

    float acc[4][4][4];
    #pragma unroll
    for (int mt = 0; mt < 4; mt++)
        #pragma unroll
        for (int nt = 0; nt < 4; nt++)
            #pragma unroll
            for (int i = 0; i < 4; i++) acc[mt][nt][i] = 0.0f;

    float4 pa0 = *(const float4*)(A  + (size_t)(m0 + lr)      * K + lc);
    float4 pa1 = *(const float4*)(A  + (size_t)(m0 + lr + 64) * K + lc);
    float4 pb0 = *(const float4*)(Bm + (size_t)(n0 + lr)      * K + lc);
    float4 pb1 = *(const float4*)(Bm + (size_t)(n0 + lr + 64) * K + lc);

    for (int k0 = 0; k0 < K; k0 += 16) {
        *(float4*)&As[lr][lc]      = make_float4(tf32r(pa0.x), tf32r(pa0.y), tf32r(pa0.z), tf32r(pa0.w));
        *(float4*)&As[lr + 64][lc] = make_float4(tf32r(pa1.x), tf32r(pa1.y), tf32r(pa1.z), tf32r(pa1.w));
        *(float4*)&Bs[lr][lc]      = make_float4(tf32r(pb0.x), tf32r(pb0.y), tf32r(pb0.z), tf32r(pb0.w));
        *(float4*)&Bs[lr + 64][lc] = make_float4(tf32r(pb1.x), tf32r(pb1.y), tf32r(pb1.z), tf32r(pb1.w));
        __syncthreads();

        if (k0 + 16 < K) {
            pa0 = *(const float4*)(A  + (size_t)(m0 + lr)      * K + k0 + 16 + lc);
            pa1 = *(const float4*)(A  + (size_t)(m0 + lr + 64) * K + k0 + 16 + lc);
            pb0 = *(const float4*)(Bm + (size_t)(n0 + lr)      * K + k0 + 16 + lc);
            pb1 = *(const float4*)(Bm + (size_t)(n0 + lr + 64) * K + k0 + 16 + lc);
        }

        #pragma unroll
        for (int ks = 0; ks < 16; ks += 8) {
            uint32_t a[4][4], b[4][2];
            #pragma unroll
            for (int mt = 0; mt < 4; mt++) {
                const int m = wm * 64 + mt * 16 + g;
                a[mt][0] = __float_as_uint(As[m][ks + tg]);
                a[mt][1] = __float_as_uint(As[m + 8][ks + tg]);
                a[mt][2] = __float_as_uint(As[m][ks + tg + 4]);
                a[mt][3] = __float_as_uint(As[m + 8][ks + tg + 4]);
            }
            #pragma unroll
            for (int nt = 0; nt < 4; nt++) {
                const int n = wn * 32 + nt * 8 + g;
                b[nt][0] = __float_as_uint(Bs[n][ks + tg]);
                b[nt][1] = __float_as_uint(Bs[n][ks + tg + 4]);
            }
            #pragma unroll
            for (int mt = 0; mt < 4; mt++)
                #pragma unroll
                for (int nt = 0; nt < 4; nt++)
                    mma8(acc[mt][nt], a[mt], b[nt]);
        }
        __syncthreads();
    }

    #pragma unroll
    for (int mt = 0; mt < 4; mt++) {
        const int m = m0 + wm * 64 + mt * 16 + g;
        #pragma unroll
        for (int nt = 0; nt < 4; nt++) {
            const int n = n0 + wn * 32 + nt * 8 + 2 * tg;
            *(float2*)(C + (size_t)m * N + n)       = make_float2(acc[mt][nt][0], acc[mt][nt][1]);
            *(float2*)(C + (size_t)(m + 8) * N + n) = make_float2(acc[mt][nt][2], acc[mt][nt][3]);
        }
    }
}

// ---------------------------------------------------------------------------
// Kernel 3: q/k LN + RoPE + transpose (tf32-rounded outputs)
// ---------------------------------------------------------------------------
__global__ void __launch_bounds__(256) qk_rope_kernel(
    const float* __restrict__ q_ln_w,
    const float* __restrict__ k_ln_w)
{
    __shared__ float sm[D];
    __shared__ float sbuf[8];

    const int t   = blockIdx.x;
    const int tid = threadIdx.x;
    const int b   = t / L;
    const int l   = t % L;

    #pragma unroll
    for (int seg = 0; seg < 2; seg++) {
        const float* base = g_qkv + (size_t)t * (3 * D) + seg * D;
        const float* w    = (seg == 0) ? q_ln_w : k_ln_w;
        float*       dst  = (seg == 0) ? g_q    : g_k;

        const float4 xv = *(const float4*)(base + 4 * tid);
        float s  = xv.x + xv.y + xv.z + xv.w;
        float ss = fmaf(xv.x, xv.x, fmaf(xv.y, xv.y, fmaf(xv.z, xv.z, xv.w * xv.w)));
        s  = block_reduce_sum_256(s,  sbuf);
        ss = block_reduce_sum_256(ss, sbuf);
        const float mu = s * (1.0f / D);
        const float rs = rsqrtf(ss * (1.0f / D) - mu * mu + EPS);

        const float4 wv = *(const float4*)(w + 4 * tid);
        sm[4 * tid + 0] = (xv.x - mu) * rs * wv.x;
        sm[4 * tid + 1] = (xv.y - mu) * rs * wv.y;
        sm[4 * tid + 2] = (xv.z - mu) * rs * wv.z;
        sm[4 * tid + 3] = (xv.w - mu) * rs * wv.w;
        __syncthreads();

        float out[4];
        #pragma unroll
        for (int c = 0; c < 4; c++) {
            int d  = 4 * tid + c;
            int dh = d & 63;
            int i  = dh & 31;
            float inv_freq = expf(-(float)(2 * i) * (1.0f / 64.0f) * LOG_ROPE_BASE);
            float freq = (float)l * inv_freq;
            float sn, cs;
            sincosf(freq, &sn, &cs);
            if (dh < 32) out[c] = sm[d] * cs - sm[d + 32] * sn;
            else         out[c] = sm[d] * cs + sm[d - 32] * sn;
        }
        const int d0   = 4 * tid;
        const int head = d0 >> 6;
        const int dh0  = d0 & 63;
        *(float4*)(dst + ((size_t)(b * H + head) * L + l) * DH + dh0) =
            make_float4(tf32r(out[0]), tf32r(out[1]), tf32r(out[2]), tf32r(out[3]));
        __syncthreads();
    }

    {
        const float4 vv = *(const float4*)(g_qkv + (size_t)t * (3 * D) + 2 * D + 4 * tid);
        const int d0   = 4 * tid;
        const int head = d0 >> 6;
        const int dh0  = d0 & 63;
        *(float4*)(g_v + ((size_t)(b * H + head) * L + l) * DH + dh0) =
            make_float4(tf32r(vv.x), tf32r(vv.y), tf32r(vv.z), tf32r(vv.w));
    }
}

// ---------------------------------------------------------------------------
// Kernel 4 (v2): flash attention, warp-owns-full-key-range design.
// grid = (L/128, B*H), 256 threads. Warp w handles q rows [q0+16w, +16),
// all 64 keys of each KV tile. Softmax fully in registers.
// smem: Ks[2][64][68], Vs[2][64][72], Pw[8][16][68] (per-warp P pad,
// also used to stage Q at startup). cp.async 2-stage pipeline for K/V.
// ---------------------------------------------------------------------------
constexpr int SKK = 68;   // Ks stride
constexpr int SVV = 72;   // Vs stride
constexpr int SPP = 68;   // Pw stride
constexpr int ATTN_SMEM_FLOATS = 2 * 64 * SKK + 2 * 64 * SVV + 8 * 16 * SPP;
constexpr size_t ATTN_SMEM_BYTES = ATTN_SMEM_FLOATS * sizeof(float);
constexpr int NKT = L / 64;   // 32 KV tiles

__global__ void __launch_bounds__(256) attn_tf32_v2(float* __restrict__ ctx)
{
    extern __shared__ float smem[];
    float* KsBuf = smem;                          // 2 x [64][68]
    float* VsBuf = smem + 2 * 64 * SKK;           // 2 x [64][72]
    float* PwAll = smem + 2 * 64 * SKK + 2 * 64 * SVV;  // 8 x [16][68]

    const int tid  = threadIdx.x;
    const int lane = tid & 31;
    const int g    = lane >> 2;
    const int tg   = lane & 3;
    const int w    = tid >> 5;
    const int bh   = blockIdx.y;
    const int bb   = bh / H;
    const int hh   = bh % H;
    const int q0   = blockIdx.x * 128;

    float* Pw = PwAll + w * 16 * SPP;
    const uint32_t ks_smem = (uint32_t)__cvta_generic_to_shared(KsBuf);
    const uint32_t vs_smem = (uint32_t)__cvta_generic_to_shared(VsBuf);

    const float* Kg0 = g_k + (size_t)bh * L * DH;
    const float* Vg0 = g_v + (size_t)bh * L * DH;

    // --- prefetch tile 0 (cp.async, buffer 0) ---
    {
        #pragma unroll
        for (int r = 0; r < 4; r++) {
            int idx  = tid + r * 256;
            int row  = idx >> 4;
            int colb = (idx & 15) * 4;
            cp_async16(ks_smem + (row * SKK + colb) * 4, Kg0 + row * DH + colb);
            cp_async16(vs_smem + (row * SVV + colb) * 4, Vg0 + row * DH + colb);
        }
        asm volatile("cp.async.commit_group;");
    }

    // --- stage this warp's Q tile into Pw, hoist fragments (scale folded) ---
    uint32_t qa[8][4];
    {
        const float* Qg = g_q + ((size_t)bh * L + q0 + w * 16) * DH;
        #pragma unroll
        for (int r = 0; r < 8; r++) {
            int idx  = lane + r * 32;          // 256 float4 slots
            int row  = idx >> 4;
            int colb = (idx & 15) * 4;
            *(float4*)&Pw[row * SPP + colb] = *(const float4*)(Qg + row * DH + colb);
        }
        __syncwarp();
        #pragma unroll
        for (int ks = 0; ks < 8; ks++) {
            qa[ks][0] = __float_as_uint(0.125f * Pw[g * SPP + ks * 8 + tg]);
            qa[ks][1] = __float_as_uint(0.125f * Pw[(g + 8) * SPP + ks * 8 + tg]);
            qa[ks][2] = __float_as_uint(0.125f * Pw[g * SPP + ks * 8 + tg + 4]);
            qa[ks][3] = __float_as_uint(0.125f * Pw[(g + 8) * SPP + ks * 8 + tg + 4]);
        }
        __syncwarp();
    }

    float m0 = -1e30f, m1 = -1e30f, l0 = 0.0f, l1 = 0.0f;
    float o[8][4];
    #pragma unroll
    for (int nt = 0; nt < 8; nt++)
        #pragma unroll
        for (int i = 0; i < 4; i++) o[nt][i] = 0.0f;

    for (int kt = 0; kt < NKT; kt++) {
        const int cur = kt & 1;

        // prefetch next tile into other buffer
        if (kt + 1 < NKT) {
            const float* Kg = Kg0 + (size_t)(kt + 1) * 64 * DH;
            const float* Vg = Vg0 + (size_t)(kt + 1) * 64 * DH;
            const uint32_t kd = ks_smem + (cur ^ 1) * 64 * SKK * 4;
            const uint32_t vd = vs_smem + (cur ^ 1) * 64 * SVV * 4;
            #pragma unroll
            for (int r = 0; r < 4; r++) {
                int idx  = tid + r * 256;
                int row  = idx >> 4;
                int colb = (idx & 15) * 4;
                cp_async16(kd + (row * SKK + colb) * 4, Kg + row * DH + colb);
                cp_async16(vd + (row * SVV + colb) * 4, Vg + row * DH + colb);
            }
        }
        asm volatile("cp.async.commit_group;");
        asm volatile("cp.async.wait_group 1;");
        __syncthreads();

        const float* Ks = KsBuf + cur * 64 * SKK;
        const float* Vs = VsBuf + cur * 64 * SVV;

        // ---- S = (Q*scale) K^T : 16 x 64 per warp ----
        float s[8][4];
        #pragma unroll
        for (int nt = 0; nt < 8; nt++)
            #pragma unroll
            for (int i = 0; i < 4; i++) s[nt][i] = 0.0f;

        #pragma unroll
        for (int ks = 0; ks < 8; ks++) {
            uint32_t bk[8][2];
            #pragma unroll
            for (int nt = 0; nt < 8; nt++) {
                const int kn = nt * 8 + g;
                bk[nt][0] = __float_as_uint(Ks[kn * SKK + ks * 8 + tg]);
                bk[nt][1] = __float_as_uint(Ks[kn * SKK + ks * 8 + tg + 4]);
            }
            #pragma unroll
            for (int nt = 0; nt < 8; nt++) mma8(s[nt], qa[ks], bk[nt]);
        }

        // ---- online softmax in registers (rows g and g+8) ----
        float mx0 = -1e30f, mx1 = -1e30f;
        #pragma unroll
        for (int nt = 0; nt < 8; nt++) {
            mx0 = fmaxf(mx0, fmaxf(s[nt][0], s[nt][1]));
            mx1 = fmaxf(mx1, fmaxf(s[nt][2], s[nt][3]));
        }
        mx0 = fmaxf(mx0, __shfl_xor_sync(0xffffffffu, mx0, 1));
        mx0 = fmaxf(mx0, __shfl_xor_sync(0xffffffffu, mx0, 2));
        mx1 = fmaxf(mx1, __shfl_xor_sync(0xffffffffu, mx1, 1));
        mx1 = fmaxf(mx1, __shfl_xor_sync(0xffffffffu, mx1, 2));
        const float nm0 = fmaxf(m0, mx0);
        const float nm1 = fmaxf(m1, mx1);

        float sum0 = 0.0f, sum1 = 0.0f;
        #pragma unroll
        for (int nt = 0; nt < 8; nt++) {
            s[nt][0] = tf32r(__expf(s[nt][0] - nm0));
            s[nt][1] = tf32r(__expf(s[nt][1] - nm0));
            s[nt][2] = tf32r(__expf(s[nt][2] - nm1));
            s[nt][3] = tf32r(__expf(s[nt][3] - nm1));
            sum0 += s[nt][0] + s[nt][1];
            sum1 += s[nt][2] + s[nt][3];
        }
        sum0 += __shfl_xor_sync(0xffffffffu, sum0, 1);
        sum0 += __shfl_xor_sync(0xffffffffu, sum0, 2);
        sum1 += __shfl_xor_sync(0xffffffffu, sum1, 1);
        sum1 += __shfl_xor_sync(0xffffffffu, sum1, 2);

        const float al0 = __expf(m0 - nm0);
        const float al1 = __expf(m1 - nm1);
        l0 = l0 * al0 + sum0;  m0 = nm0;
        l1 = l1 * al1 + sum1;  m1 = nm1;

        // ---- store P (warp-private), rescale O ----
        #pragma unroll
        for (int nt = 0; nt < 8; nt++) {
            *(float2*)&Pw[g * SPP + nt * 8 + 2 * tg]       = make_float2(s[nt][0], s[nt][1]);
            *(float2*)&Pw[(g + 8) * SPP + nt * 8 + 2 * tg] = make_float2(s[nt][2], s[nt][3]);
        }
        #pragma unroll
        for (int nt = 0; nt < 8; nt++) {
            o[nt][0] *= al0; o[nt][1] *= al0;
            o[nt][2] *= al1; o[nt][3] *= al1;
        }
        __syncwarp();

        // ---- O += P @ V ----
        #pragma unroll
        for (int ks = 0; ks < 8; ks++) {
            uint32_t a[4];
            a[0] = __float_as_uint(Pw[g * SPP + ks * 8 + tg]);
            a[1] = __float_as_uint(Pw[(g + 8) * SPP + ks * 8 + tg]);
            a[2] = __float_as_uint(Pw[g * SPP + ks * 8 + tg + 4]);
            a[3] = __float_as_uint(Pw[(g + 8) * SPP + ks * 8 + tg + 4]);
            #pragma unroll
            for (int nt = 0; nt < 8; nt++) {
                uint32_t bv[2];
                bv[0] = __float_as_uint(Vs[(ks * 8 + tg) * SVV + nt * 8 + g]);
                bv[1] = __float_as_uint(Vs[(ks * 8 + tg + 4) * SVV + nt * 8 + g]);
                mma8(o[nt], a, bv);
            }
        }
        __syncthreads();   // everyone done with cur buffers before reuse
    }

    // ---- epilogue ----
    const float inv0 = 1.0f / l0;
    const float inv1 = 1.0f / l1;
    const int row0 = q0 + w * 16 + g;
    const int row1 = row0 + 8;
    #pragma unroll
    for (int nt = 0; nt < 8; nt++) {
        const int col = hh * DH + nt * 8 + 2 * tg;
        *(float2*)(ctx + (size_t)(bb * L + row0) * D + col) =
            make_float2(o[nt][0] * inv0, o[nt][1] * inv0);
        *(float2*)(ctx + (size_t)(bb * L + row1) * D + col) =
            make_float2(o[nt][2] * inv1, o[nt][3] * inv1);
    }
}

// ---------------------------------------------------------------------------
// Launch
// ---------------------------------------------------------------------------
extern "C" void kernel_launch(void* const* d_in, const int* in_sizes, int n_in,
                              void* d_out, int out_size)
{
    const float* x      = (const float*)d_in[0];
    const float* ln_w   = (const float*)d_in[1];
    const float* ln_b   = (const float*)d_in[2];
    const float* w_qkv  = (const float*)d_in[3];
    const float* q_ln_w = (const float*)d_in[4];
    const float* k_ln_w = (const float*)d_in[5];
    const float* w_out  = (const float*)d_in[6];
    float* out = (float*)d_out;

    float *h, *qkv, *ctx;
    cudaGetSymbolAddress((void**)&h,   g_h);
    cudaGetSymbolAddress((void**)&qkv, g_qkv);
    cudaGetSymbolAddress((void**)&ctx, g_ctx);

    cudaFuncSetAttribute(attn_tf32_v2, cudaFuncAttributeMaxDynamicSharedMemorySize,
                         (int)ATTN_SMEM_BYTES);

    // 1. LN(x) -> g_h
    ln_kernel<<<BL, 256>>>(x, ln_w, ln_b);

    // 2. qkv = h @ w_qkv^T   [4096, 3072]
    {
        dim3 grid(3 * D / 128, BL / 128);
        gemm_nt_tf32<<<grid, 256>>>(h, w_qkv, qkv, BL, 3 * D, D);
    }

    // 3. q/k LN + RoPE + transpose (tf32-rounded), v transpose
    qk_rope_kernel<<<BL, 256>>>(q_ln_w, k_ln_w);

    // 4. attention -> g_ctx  [B,L,H*DH]
    {
        dim3 grid(L / 128, B * H);
        attn_tf32_v2<<<grid, 256, ATTN_SMEM_BYTES>>>(ctx);
    }

    // 5. out = ctx @ w_out^T  [4096, 1024]
    {
        dim3 grid(D / 128, BL / 128);
        gemm_nt_tf32<<<grid, 256>>>(ctx, w_out, out, BL, D, D);
    }
}

// round 6
// speedup vs baseline: 2.0064x; 2.0064x over previous
#include <cuda_runtime.h>
#include <cuda_fp16.h>
#include <math.h>
#include <stdint.h>

constexpr int B  = 2;
constexpr int L  = 2048;
constexpr int D  = 1024;
constexpr int H  = 16;
constexpr int DH = 64;
constexpr int BL = B * L;
constexpr float EPS = 1e-5f;
constexpr float LOG_ROPE_BASE = 9.210340371976184f;

// Scratch
__device__ __half g_h_h[BL * D];
__device__ __half g_wqkv_h[3 * D * D];
__device__ __half g_wout_h[D * D];
__device__ float  g_qkv[BL * 3 * D];
__device__ __half g_qh[BL * D];     // pre-scaled by 1/8
__device__ __half g_kh[BL * D];
__device__ __half g_vh[BL * D];
__device__ __half g_ctx_h[BL * D];

// Helpers
__device__ __forceinline__ uint32_t smem_u32(const void* p) {
    return (uint32_t)__cvta_generic_to_shared(p);
}
__device__ __forceinline__ void cp_async16(uint32_t dst, const void* src) {
    asm volatile("cp.async.cg.shared.global [%0], [%1], 16;" :: "r"(dst), "l"(src));
}
#define CP_COMMIT() asm volatile("cp.async.commit_group;")
#define CP_WAIT1()  asm volatile("cp.async.wait_group 1;")
#define LDMX4(r0,r1,r2,r3,addr) \
    asm volatile("ldmatrix.sync.aligned.m8n8.x4.shared.b16 {%0,%1,%2,%3},[%4];" \
                 : "=r"(r0),"=r"(r1),"=r"(r2),"=r"(r3) : "r"(addr))
#define LDMX4T(r0,r1,r2,r3,addr) \
    asm volatile("ldmatrix.sync.aligned.m8n8.x4.trans.shared.b16 {%0,%1,%2,%3},[%4];" \
                 : "=r"(r0),"=r"(r1),"=r"(r2),"=r"(r3) : "r"(addr))

__device__ __forceinline__ void mma16(float* c, const uint32_t* a, const uint32_t* b) {
    asm volatile(
        "mma.sync.aligned.m16n8k16.row.col.f32.f16.f16.f32 "
        "{%0,%1,%2,%3},{%4,%5,%6,%7},{%8,%9},{%0,%1,%2,%3};"
        : "+f"(c[0]), "+f"(c[1]), "+f"(c[2]), "+f"(c[3])
        : "r"(a[0]), "r"(a[1]), "r"(a[2]), "r"(a[3]), "r"(b[0]), "r"(b[1]));
}

__device__ __forceinline__ float block_reduce_sum_256(float v, float* sbuf) {
    int tid = threadIdx.x;
    #pragma unroll
    for (int o = 16; o > 0; o >>= 1) v += __shfl_xor_sync(0xffffffffu, v, o);
    if ((tid & 31) == 0) sbuf[tid >> 5] = v;
    __syncthreads();
    if (tid < 8) {
        float w = sbuf[tid];
        #pragma unroll
        for (int o = 4; o > 0; o >>= 1) w += __shfl_xor_sync(0xffu, w, o);
        if (tid == 0) sbuf[0] = w;
    }
    __syncthreads();
    float r = sbuf[0];
    __syncthreads();
    return r;
}

// Kernel 0: weights -> fp16
__global__ void __launch_bounds__(256) prep_w(
    const float* __restrict__ wq, const float* __restrict__ wo)
{
    const size_t i4 = ((size_t)blockIdx.x * 256 + threadIdx.x) * 4;
    const size_t n1 = (size_t)3 * D * D;
    if (i4 < n1) {
        float4 v = *(const float4*)(wq + i4);
        *(__half2*)(g_wqkv_h + i4)     = __floats2half2_rn(v.x, v.y);
        *(__half2*)(g_wqkv_h + i4 + 2) = __floats2half2_rn(v.z, v.w);
    } else {
        size_t j = i4 - n1;
        float4 v = *(const float4*)(wo + j);
        *(__half2*)(g_wout_h + j)     = __floats2half2_rn(v.x, v.y);
        *(__half2*)(g_wout_h + j + 2) = __floats2half2_rn(v.z, v.w);
    }
}

// Kernel 1: LayerNorm -> fp16 hidden
__global__ void __launch_bounds__(256) ln_kernel(
    const float* __restrict__ x, const float* __restrict__ w,
    const float* __restrict__ bias)
{
    __shared__ float sbuf[8];
    const int t = blockIdx.x, tid = threadIdx.x;
    const float4 xv = *(const float4*)(x + (size_t)t * D + 4 * tid);
    float s  = xv.x + xv.y + xv.z + xv.w;
    float ss = fmaf(xv.x, xv.x, fmaf(xv.y, xv.y, fmaf(xv.z, xv.z, xv.w * xv.w)));
    s  = block_reduce_sum_256(s,  sbuf);
    ss = block_reduce_sum_256(ss, sbuf);
    const float mu = s * (1.0f / D);
    const float rs = rsqrtf(ss * (1.0f / D) - mu * mu + EPS);
    const float4 wv = *(const float4*)(w    + 4 * tid);
    const float4 bv = *(const float4*)(bias + 4 * tid);
    __half* dst = g_h_h + (size_t)t * D + 4 * tid;
    *(__half2*)(dst)     = __floats2half2_rn((xv.x - mu) * rs * wv.x + bv.x,
                                             (xv.y - mu) * rs * wv.y + bv.y);
    *(__half2*)(dst + 2) = __floats2half2_rn((xv.z - mu) * rs * wv.z + bv.z,
                                             (xv.w - mu) * rs * wv.w + bv.w);
}

// Kernel 2/5: fp16 GEMM-NT, C fp32. 128x128, k-stage 32, 3-stage cp.async.
constexpr int GST  = 40;                 // halves per row (80B, conflict-free)
constexpr int GBUF = 128 * GST * 2;      // bytes per stage per matrix
constexpr int GEMM_SMEM = 6 * GBUF;      // 61440 B

__global__ void __launch_bounds__(256) gemm_nt_f16(
    const __half* __restrict__ A, const __half* __restrict__ Bm,
    float* __restrict__ C, int M, int N, int K)
{
    extern __shared__ __half gsm[];
    const uint32_t as0 = smem_u32(gsm);
    const uint32_t bs0 = smem_u32(gsm + 3 * 128 * GST);

    const int tid  = threadIdx.x;
    const int lane = tid & 31;
    const int g    = lane >> 2;
    const int tg   = lane & 3;
    const int wid  = tid >> 5;
    const int wm   = wid >> 2;
    const int wn   = wid & 3;
    const int m0   = blockIdx.y * 128;
    const int n0   = blockIdx.x * 128;

    float acc[4][4][4];
    #pragma unroll
    for (int mt = 0; mt < 4; mt++)
        #pragma unroll
        for (int nt = 0; nt < 4; nt++)
            #pragma unroll
            for (int i = 0; i < 4; i++) acc[mt][nt][i] = 0.0f;

    auto stage = [&](int s, int k0) {
        #pragma unroll
        for (int r = 0; r < 2; r++) {
            int qid = tid + r * 256;
            int row = qid >> 2;
            int cq  = (qid & 3) * 8;
            cp_async16(as0 + s * GBUF + (row * GST + cq) * 2,
                       A + (size_t)(m0 + row) * K + k0 + cq);
            cp_async16(bs0 + s * GBUF + (row * GST + cq) * 2,
                       Bm + (size_t)(n0 + row) * K + k0 + cq);
        }
    };
    stage(0, 0);  CP_COMMIT();
    stage(1, 32); CP_COMMIT();

    const uint32_t a_lane = ((lane & 15) * GST + (lane >> 4) * 8) * 2;
    const uint32_t b_lane = ((((lane >> 4) << 3) + (lane & 7)) * GST +
                             ((lane >> 3) & 1) * 8) * 2;

    const int NIT = K / 32;
    for (int kt = 0; kt < NIT; kt++) {
        CP_WAIT1();
        __syncthreads();
        if (kt + 2 < NIT) stage((kt + 2) % 3, (kt + 2) * 32);
        CP_COMMIT();

        const uint32_t ab = as0 + (kt % 3) * GBUF + (wm * 64) * GST * 2 + a_lane;
        const uint32_t bb = bs0 + (kt % 3) * GBUF + (wn * 32) * GST * 2 + b_lane;

        #pragma unroll
        for (int kk = 0; kk < 2; kk++) {
            uint32_t bf[4][2];
            #pragma unroll
            for (int p = 0; p < 2; p++)
                LDMX4(bf[2*p][0], bf[2*p][1], bf[2*p+1][0], bf[2*p+1][1],
                      bb + p * 16 * GST * 2 + kk * 32);
            #pragma unroll
            for (int mt = 0; mt < 4; mt++) {
                uint32_t a[4];
                LDMX4(a[0], a[1], a[2], a[3], ab + mt * 16 * GST * 2 + kk * 32);
                #pragma unroll
                for (int nt = 0; nt < 4; nt++) mma16(acc[mt][nt], a, bf[nt]);
            }
        }
    }

    #pragma unroll
    for (int mt = 0; mt < 4; mt++) {
        const int m = m0 + wm * 64 + mt * 16 + g;
        #pragma unroll
        for (int nt = 0; nt < 4; nt++) {
            const int n = n0 + wn * 32 + nt * 8 + 2 * tg;
            *(float2*)(C + (size_t)m * N + n)       = make_float2(acc[mt][nt][0], acc[mt][nt][1]);
            *(float2*)(C + (size_t)(m + 8) * N + n) = make_float2(acc[mt][nt][2], acc[mt][nt][3]);
        }
    }
}

// Kernel 3: q/k LN + RoPE + transpose, fp16 outputs (q pre-scaled 1/8)
__global__ void __launch_bounds__(256) qk_rope_kernel(
    const float* __restrict__ q_ln_w, const float* __restrict__ k_ln_w)
{
    __shared__ float sm[D];
    __shared__ float sbuf[8];
    const int t = blockIdx.x, tid = threadIdx.x;
    const int b = t / L, l = t % L;

    #pragma unroll
    for (int seg = 0; seg < 2; seg++) {
        const float* base = g_qkv + (size_t)t * (3 * D) + seg * D;
        const float* w    = (seg == 0) ? q_ln_w : k_ln_w;
        __half*      dst  = (seg == 0) ? g_qh   : g_kh;
        const float  osc  = (seg == 0) ? 0.125f : 1.0f;

        const float4 xv = *(const float4*)(base + 4 * tid);
        float s  = xv.x + xv.y + xv.z + xv.w;
        float ss = fmaf(xv.x, xv.x, fmaf(xv.y, xv.y, fmaf(xv.z, xv.z, xv.w * xv.w)));
        s  = block_reduce_sum_256(s,  sbuf);
        ss = block_reduce_sum_256(ss, sbuf);
        const float mu = s * (1.0f / D);
        const float rs = rsqrtf(ss * (1.0f / D) - mu * mu + EPS);

        const float4 wv = *(const float4*)(w + 4 * tid);
        sm[4 * tid + 0] = (xv.x - mu) * rs * wv.x;
        sm[4 * tid + 1] = (xv.y - mu) * rs * wv.y;
        sm[4 * tid + 2] = (xv.z - mu) * rs * wv.z;
        sm[4 * tid + 3] = (xv.w - mu) * rs * wv.w;
        __syncthreads();

        float out[4];
        #pragma unroll
        for (int c = 0; c < 4; c++) {
            int d  = 4 * tid + c;
            int dh = d & 63;
            int i  = dh & 31;
            float inv_freq = expf(-(float)(2 * i) * (1.0f / 64.0f) * LOG_ROPE_BASE);
            float sn, cs;
            sincosf((float)l * inv_freq, &sn, &cs);
            if (dh < 32) out[c] = sm[d] * cs - sm[d + 32] * sn;
            else         out[c] = sm[d] * cs + sm[d - 32] * sn;
        }
        const int d0 = 4 * tid, head = d0 >> 6, dh0 = d0 & 63;
        __half* dp = dst + ((size_t)(b * H + head) * L + l) * DH + dh0;
        *(__half2*)(dp)     = __floats2half2_rn(out[0] * osc, out[1] * osc);
        *(__half2*)(dp + 2) = __floats2half2_rn(out[2] * osc, out[3] * osc);
        __syncthreads();
    }
    {
        const float4 vv = *(const float4*)(g_qkv + (size_t)t * (3 * D) + 2 * D + 4 * tid);
        const int d0 = 4 * tid, head = d0 >> 6, dh0 = d0 & 63;
        __half* dp = g_vh + ((size_t)(b * H + head) * L + l) * DH + dh0;
        *(__half2*)(dp)     = __floats2half2_rn(vv.x, vv.y);
        *(__half2*)(dp + 2) = __floats2half2_rn(vv.z, vv.w);
    }
}

// Kernel 4: fp16 flash attention, ldmatrix + m16n8k16.
// grid=(L/128, B*H), 256 thr; warp w owns q rows [q0+16w,+16), all 64 keys.
constexpr int AST = 72;                       // halves per row (144B)
constexpr int AKB = 64 * AST;                 // halves per K/V stage
constexpr int ATTN_SMEM = (4 * AKB + 8 * 16 * AST) * 2;  // 55296 B
constexpr int NKT = L / 64;

__global__ void __launch_bounds__(256) attn_f16(__half* __restrict__ ctx)
{
    extern __shared__ __half hsm[];
    const uint32_t ks0 = smem_u32(hsm);
    const uint32_t vs0 = smem_u32(hsm + 2 * AKB);
    __half* Pw = hsm + 4 * AKB + (threadIdx.x >> 5) * 16 * AST;
    const uint32_t pw0 = smem_u32(Pw);

    const int tid  = threadIdx.x;
    const int lane = tid & 31;
    const int g    = lane >> 2;
    const int tg   = lane & 3;
    const int w    = tid >> 5;
    const int bh   = blockIdx.y;
    const int bb   = bh / H;
    const int hh   = bh % H;
    const int q0   = blockIdx.x * 128;

    const __half* Kg0 = g_kh + (size_t)bh * L * DH;
    const __half* Vg0 = g_vh + (size_t)bh * L * DH;

    // prefetch tile 0 -> buf 0
    #pragma unroll
    for (int r = 0; r < 2; r++) {
        int idx = tid + r * 256;
        int row = idx >> 3, col = (idx & 7) * 8;
        cp_async16(ks0 + (row * AST + col) * 2, Kg0 + row * DH + col);
        cp_async16(vs0 + (row * AST + col) * 2, Vg0 + row * DH + col);
    }
    CP_COMMIT();

    // stage this warp's Q (fp16, pre-scaled), hoist fragments
    uint32_t qa[4][4];
    {
        const __half* Qg = g_qh + ((size_t)bh * L + q0 + w * 16) * DH;
        #pragma unroll
        for (int r = 0; r < 4; r++) {
            int idx = lane + r * 32;
            int row = idx >> 3, col = (idx & 7) * 8;
            *(float4*)&Pw[row * AST + col] = *(const float4*)(Qg + row * DH + col);
        }
        __syncwarp();
        const uint32_t qaddr = pw0 + ((lane & 15) * AST + (lane >> 4) * 8) * 2;
        #pragma unroll
        for (int ks = 0; ks < 4; ks++)
            LDMX4(qa[ks][0], qa[ks][1], qa[ks][2], qa[ks][3], qaddr + ks * 32);
        __syncwarp();
    }

    float m0 = -1e30f, m1 = -1e30f, l0 = 0.0f, l1 = 0.0f;
    float o[8][4];
    #pragma unroll
    for (int nt = 0; nt < 8; nt++)
        #pragma unroll
        for (int i = 0; i < 4; i++) o[nt][i] = 0.0f;

    // lane components for K (non-trans) and V (trans) ldmatrix
    const uint32_t k_lane = (((lane & 7) + ((lane >> 4) << 3)) * AST +
                             ((lane >> 3) & 1) * 8) * 2;
    const uint32_t v_lane = (((lane & 7) + (((lane >> 3) & 1) << 3)) * AST +
                             ((lane >> 4) << 3)) * 2;

    for (int kt = 0; kt < NKT; kt++) {
        const int cur = kt & 1;
        if (kt + 1 < NKT) {
            const __half* Kg = Kg0 + (size_t)(kt + 1) * 64 * DH;
            const __half* Vg = Vg0 + (size_t)(kt + 1) * 64 * DH;
            const uint32_t kd = ks0 + (cur ^ 1) * AKB * 2;
            const uint32_t vd = vs0 + (cur ^ 1) * AKB * 2;
            #pragma unroll
            for (int r = 0; r < 2; r++) {
                int idx = tid + r * 256;
                int row = idx >> 3, col = (idx & 7) * 8;
                cp_async16(kd + (row * AST + col) * 2, Kg + row * DH + col);
                cp_async16(vd + (row * AST + col) * 2, Vg + row * DH + col);
            }
        }
        CP_COMMIT();
        CP_WAIT1();
        __syncthreads();

        const uint32_t ksb = ks0 + cur * AKB * 2;
        const uint32_t vsb = vs0 + cur * AKB * 2;

        // S = (Q/8) K^T : 16x64
        float s[8][4];
        #pragma unroll
        for (int nt = 0; nt < 8; nt++)
            #pragma unroll
            for (int i = 0; i < 4; i++) s[nt][i] = 0.0f;

        #pragma unroll
        for (int ks = 0; ks < 4; ks++) {
            uint32_t bk[8][2];
            #pragma unroll
            for (int p = 0; p < 4; p++)
                LDMX4(bk[2*p][0], bk[2*p][1], bk[2*p+1][0], bk[2*p+1][1],
                      ksb + p * 16 * AST * 2 + ks * 32 + k_lane);
            #pragma unroll
            for (int nt = 0; nt < 8; nt++) mma16(s[nt], qa[ks], bk[nt]);
        }

        // online softmax in registers
        float mx0 = -1e30f, mx1 = -1e30f;
        #pragma unroll
        for (int nt = 0; nt < 8; nt++) {
            mx0 = fmaxf(mx0, fmaxf(s[nt][0], s[nt][1]));
            mx1 = fmaxf(mx1, fmaxf(s[nt][2], s[nt][3]));
        }
        mx0 = fmaxf(mx0, __shfl_xor_sync(0xffffffffu, mx0, 1));
        mx0 = fmaxf(mx0, __shfl_xor_sync(0xffffffffu, mx0, 2));
        mx1 = fmaxf(mx1, __shfl_xor_sync(0xffffffffu, mx1, 1));
        mx1 = fmaxf(mx1, __shfl_xor_sync(0xffffffffu, mx1, 2));
        const float nm0 = fmaxf(m0, mx0);
        const float nm1 = fmaxf(m1, mx1);

        float sum0 = 0.0f, sum1 = 0.0f;
        __half2 ph[8][2];
        #pragma unroll
        for (int nt = 0; nt < 8; nt++) {
            __half2 h01 = __floats2half2_rn(__expf(s[nt][0] - nm0), __expf(s[nt][1] - nm0));
            __half2 h23 = __floats2half2_rn(__expf(s[nt][2] - nm1), __expf(s[nt][3] - nm1));
            float2 f01 = __half22float2(h01);
            float2 f23 = __half22float2(h23);
            sum0 += f01.x + f01.y;
            sum1 += f23.x + f23.y;
            ph[nt][0] = h01; ph[nt][1] = h23;
        }
        sum0 += __shfl_xor_sync(0xffffffffu, sum0, 1);
        sum0 += __shfl_xor_sync(0xffffffffu, sum0, 2);
        sum1 += __shfl_xor_sync(0xffffffffu, sum1, 1);
        sum1 += __shfl_xor_sync(0xffffffffu, sum1, 2);

        const float al0 = __expf(m0 - nm0);
        const float al1 = __expf(m1 - nm1);
        l0 = l0 * al0 + sum0;  m0 = nm0;
        l1 = l1 * al1 + sum1;  m1 = nm1;

        // store P fp16 (warp-private), rescale O
        #pragma unroll
        for (int nt = 0; nt < 8; nt++) {
            *(__half2*)&Pw[g * AST + nt * 8 + 2 * tg]       = ph[nt][0];
            *(__half2*)&Pw[(g + 8) * AST + nt * 8 + 2 * tg] = ph[nt][1];
            o[nt][0] *= al0; o[nt][1] *= al0;
            o[nt][2] *= al1; o[nt][3] *= al1;
        }
        __syncwarp();

        // O += P @ V
        #pragma unroll
        for (int ks = 0; ks < 4; ks++) {
            uint32_t a[4];
            LDMX4(a[0], a[1], a[2], a[3],
                  pw0 + ((lane & 15) * AST + (lane >> 4) * 8) * 2 + ks * 32);
            #pragma unroll
            for (int p = 0; p < 4; p++) {
                uint32_t b0, b1, b2, b3;
                LDMX4T(b0, b1, b2, b3,
                       vsb + (ks * 16) * AST * 2 + p * 32 + v_lane);
                uint32_t bA[2] = {b0, b1}, bB[2] = {b2, b3};
                mma16(o[2*p],     a, bA);
                mma16(o[2*p + 1], a, bB);
            }
        }
        __syncthreads();
    }

    // epilogue -> fp16 ctx
    const float inv0 = 1.0f / l0;
    const float inv1 = 1.0f / l1;
    const int row0 = q0 + w * 16 + g;
    const int row1 = row0 + 8;
    #pragma unroll
    for (int nt = 0; nt < 8; nt++) {
        const int col = hh * DH + nt * 8 + 2 * tg;
        *(__half2*)(ctx + (size_t)(bb * L + row0) * D + col) =
            __floats2half2_rn(o[nt][0] * inv0, o[nt][1] * inv0);
        *(__half2*)(ctx + (size_t)(bb * L + row1) * D + col) =
            __floats2half2_rn(o[nt][2] * inv1, o[nt][3] * inv1);
    }
}

// Launch
extern "C" void kernel_launch(void* const* d_in, const int* in_sizes, int n_in,
                              void* d_out, int out_size)
{
    const float* x      = (const float*)d_in[0];
    const float* ln_w   = (const float*)d_in[1];
    const float* ln_b   = (const float*)d_in[2];
    const float* w_qkv  = (const float*)d_in[3];
    const float* q_ln_w = (const float*)d_in[4];
    const float* k_ln_w = (const float*)d_in[5];
    const float* w_out  = (const float*)d_in[6];
    float* out = (float*)d_out;

    __half *hh, *wq, *wo, *ctx;
    float* qkv;
    cudaGetSymbolAddress((void**)&hh,  g_h_h);
    cudaGetSymbolAddress((void**)&wq,  g_wqkv_h);
    cudaGetSymbolAddress((void**)&wo,  g_wout_h);
    cudaGetSymbolAddress((void**)&qkv, g_qkv);
    cudaGetSymbolAddress((void**)&ctx, g_ctx_h);

    cudaFuncSetAttribute(gemm_nt_f16, cudaFuncAttributeMaxDynamicSharedMemorySize, GEMM_SMEM);
    cudaFuncSetAttribute(attn_f16,    cudaFuncAttributeMaxDynamicSharedMemorySize, ATTN_SMEM);

    prep_w<<<4096, 256>>>(w_qkv, w_out);
    ln_kernel<<<BL, 256>>>(x, ln_w, ln_b);
    {
        dim3 grid(3 * D / 128, BL / 128);
        gemm_nt_f16<<<grid, 256, GEMM_SMEM>>>(hh, wq, qkv, BL, 3 * D, D);
    }
    qk_rope_kernel<<<BL, 256>>>(q_ln_w, k_ln_w);
    {
        dim3 grid(L / 128, B * H);
        attn_f16<<<grid, 256, ATTN_SMEM>>>(ctx);
    }
    {
        dim3 grid(D / 128, BL / 128);
        gemm_nt_f16<<<grid, 256, GEMM_SMEM>>>(ctx, wo, out, BL, D, D);
    }
}

// round 7
// speedup vs baseline: 2.0558x; 1.0246x over previous
#include <cuda_runtime.h>
#include <cuda_fp16.h>
#include <math.h>
#include <stdint.h>

constexpr int B  = 2;
constexpr int L  = 2048;
constexpr int D  = 1024;
constexpr int H  = 16;
constexpr int DH = 64;
constexpr int BL = B * L;
constexpr float EPS = 1e-5f;
constexpr float LOG_ROPE_BASE = 9.210340371976184f;

// Scratch
__device__ __half g_h_h[BL * D];
__device__ __half g_wqkv_h[3 * D * D];
__device__ __half g_wout_h[D * D];
__device__ __half g_qkv_h[BL * 3 * D];
__device__ __half g_qh[BL * D];     // pre-scaled by 1/8
__device__ __half g_kh[BL * D];
__device__ __half g_vh[BL * D];
__device__ __half g_ctx_h[BL * D];
__device__ float2 g_rope[L * 32];   // cos,sin per (l, i)

// Helpers
__device__ __forceinline__ uint32_t smem_u32(const void* p) {
    return (uint32_t)__cvta_generic_to_shared(p);
}
__device__ __forceinline__ void cp_async16(uint32_t dst, const void* src) {
    asm volatile("cp.async.cg.shared.global [%0], [%1], 16;" :: "r"(dst), "l"(src));
}
#define CP_COMMIT() asm volatile("cp.async.commit_group;")
#define CP_WAIT1()  asm volatile("cp.async.wait_group 1;")
#define LDMX4(r0,r1,r2,r3,addr) \
    asm volatile("ldmatrix.sync.aligned.m8n8.x4.shared.b16 {%0,%1,%2,%3},[%4];" \
                 : "=r"(r0),"=r"(r1),"=r"(r2),"=r"(r3) : "r"(addr))
#define LDMX4T(r0,r1,r2,r3,addr) \
    asm volatile("ldmatrix.sync.aligned.m8n8.x4.trans.shared.b16 {%0,%1,%2,%3},[%4];" \
                 : "=r"(r0),"=r"(r1),"=r"(r2),"=r"(r3) : "r"(addr))

__device__ __forceinline__ void mma16(float* c, const uint32_t* a, const uint32_t* b) {
    asm volatile(
        "mma.sync.aligned.m16n8k16.row.col.f32.f16.f16.f32 "
        "{%0,%1,%2,%3},{%4,%5,%6,%7},{%8,%9},{%0,%1,%2,%3};"
        : "+f"(c[0]), "+f"(c[1]), "+f"(c[2]), "+f"(c[3])
        : "r"(a[0]), "r"(a[1]), "r"(a[2]), "r"(a[3]), "r"(b[0]), "r"(b[1]));
}

__device__ __forceinline__ uint32_t packh2(float a, float b) {
    __half2 h = __floats2half2_rn(a, b);
    return *(uint32_t*)&h;
}

__device__ __forceinline__ float block_reduce_sum_256(float v, float* sbuf) {
    int tid = threadIdx.x;
    #pragma unroll
    for (int o = 16; o > 0; o >>= 1) v += __shfl_xor_sync(0xffffffffu, v, o);
    if ((tid & 31) == 0) sbuf[tid >> 5] = v;
    __syncthreads();
    if (tid < 8) {
        float w = sbuf[tid];
        #pragma unroll
        for (int o = 4; o > 0; o >>= 1) w += __shfl_xor_sync(0xffu, w, o);
        if (tid == 0) sbuf[0] = w;
    }
    __syncthreads();
    float r = sbuf[0];
    __syncthreads();
    return r;
}

// Kernel 0a: weights -> fp16
__global__ void __launch_bounds__(256) prep_w(
    const float* __restrict__ wq, const float* __restrict__ wo)
{
    const size_t i4 = ((size_t)blockIdx.x * 256 + threadIdx.x) * 4;
    const size_t n1 = (size_t)3 * D * D;
    if (i4 < n1) {
        float4 v = *(const float4*)(wq + i4);
        *(__half2*)(g_wqkv_h + i4)     = __floats2half2_rn(v.x, v.y);
        *(__half2*)(g_wqkv_h + i4 + 2) = __floats2half2_rn(v.z, v.w);
    } else {
        size_t j = i4 - n1;
        float4 v = *(const float4*)(wo + j);
        *(__half2*)(g_wout_h + j)     = __floats2half2_rn(v.x, v.y);
        *(__half2*)(g_wout_h + j + 2) = __floats2half2_rn(v.z, v.w);
    }
}

// Kernel 0b: RoPE angle table (same fp32 chain as before -> identical values)
__global__ void __launch_bounds__(256) rope_table()
{
    const int idx = blockIdx.x * 256 + threadIdx.x;   // 0..65535
    const int l = idx >> 5;
    const int i = idx & 31;
    float inv_freq = expf(-(float)(2 * i) * (1.0f / 64.0f) * LOG_ROPE_BASE);
    float sn, cs;
    sincosf((float)l * inv_freq, &sn, &cs);
    g_rope[idx] = make_float2(cs, sn);
}

// Kernel 1: LayerNorm -> fp16 hidden
__global__ void __launch_bounds__(256) ln_kernel(
    const float* __restrict__ x, const float* __restrict__ w,
    const float* __restrict__ bias)
{
    __shared__ float sbuf[8];
    const int t = blockIdx.x, tid = threadIdx.x;
    const float4 xv = *(const float4*)(x + (size_t)t * D + 4 * tid);
    float s  = xv.x + xv.y + xv.z + xv.w;
    float ss = fmaf(xv.x, xv.x, fmaf(xv.y, xv.y, fmaf(xv.z, xv.z, xv.w * xv.w)));
    s  = block_reduce_sum_256(s,  sbuf);
    ss = block_reduce_sum_256(ss, sbuf);
    const float mu = s * (1.0f / D);
    const float rs = rsqrtf(ss * (1.0f / D) - mu * mu + EPS);
    const float4 wv = *(const float4*)(w    + 4 * tid);
    const float4 bv = *(const float4*)(bias + 4 * tid);
    __half* dst = g_h_h + (size_t)t * D + 4 * tid;
    *(__half2*)(dst)     = __floats2half2_rn((xv.x - mu) * rs * wv.x + bv.x,
                                             (xv.y - mu) * rs * wv.y + bv.y);
    *(__half2*)(dst + 2) = __floats2half2_rn((xv.z - mu) * rs * wv.z + bv.z,
                                             (xv.w - mu) * rs * wv.w + bv.w);
}

// Kernel 2/5: fp16 GEMM-NT, templated output type.
constexpr int GST  = 40;
constexpr int GBUF = 128 * GST * 2;
constexpr int GEMM_SMEM = 6 * GBUF;

__device__ __forceinline__ void store2(float* p, float a, float b) {
    *(float2*)p = make_float2(a, b);
}
__device__ __forceinline__ void store2(__half* p, float a, float b) {
    *(__half2*)p = __floats2half2_rn(a, b);
}

template <typename TOut>
__global__ void __launch_bounds__(256) gemm_nt_f16(
    const __half* __restrict__ A, const __half* __restrict__ Bm,
    TOut* __restrict__ C, int M, int N, int K)
{
    extern __shared__ __half gsm[];
    const uint32_t as0 = smem_u32(gsm);
    const uint32_t bs0 = smem_u32(gsm + 3 * 128 * GST);

    const int tid  = threadIdx.x;
    const int lane = tid & 31;
    const int g    = lane >> 2;
    const int tg   = lane & 3;
    const int wid  = tid >> 5;
    const int wm   = wid >> 2;
    const int wn   = wid & 3;
    const int m0   = blockIdx.y * 128;
    const int n0   = blockIdx.x * 128;

    float acc[4][4][4];
    #pragma unroll
    for (int mt = 0; mt < 4; mt++)
        #pragma unroll
        for (int nt = 0; nt < 4; nt++)
            #pragma unroll
            for (int i = 0; i < 4; i++) acc[mt][nt][i] = 0.0f;

    auto stage = [&](int s, int k0) {
        #pragma unroll
        for (int r = 0; r < 2; r++) {
            int qid = tid + r * 256;
            int row = qid >> 2;
            int cq  = (qid & 3) * 8;
            cp_async16(as0 + s * GBUF + (row * GST + cq) * 2,
                       A + (size_t)(m0 + row) * K + k0 + cq);
            cp_async16(bs0 + s * GBUF + (row * GST + cq) * 2,
                       Bm + (size_t)(n0 + row) * K + k0 + cq);
        }
    };
    stage(0, 0);  CP_COMMIT();
    stage(1, 32); CP_COMMIT();

    const uint32_t a_lane = ((lane & 15) * GST + (lane >> 4) * 8) * 2;
    const uint32_t b_lane = ((((lane >> 4) << 3) + (lane & 7)) * GST +
                             ((lane >> 3) & 1) * 8) * 2;

    const int NIT = K / 32;
    for (int kt = 0; kt < NIT; kt++) {
        CP_WAIT1();
        __syncthreads();
        if (kt + 2 < NIT) stage((kt + 2) % 3, (kt + 2) * 32);
        CP_COMMIT();

        const uint32_t ab = as0 + (kt % 3) * GBUF + (wm * 64) * GST * 2 + a_lane;
        const uint32_t bb = bs0 + (kt % 3) * GBUF + (wn * 32) * GST * 2 + b_lane;

        #pragma unroll
        for (int kk = 0; kk < 2; kk++) {
            uint32_t bf[4][2];
            #pragma unroll
            for (int p = 0; p < 2; p++)
                LDMX4(bf[2*p][0], bf[2*p][1], bf[2*p+1][0], bf[2*p+1][1],
                      bb + p * 16 * GST * 2 + kk * 32);
            #pragma unroll
            for (int mt = 0; mt < 4; mt++) {
                uint32_t a[4];
                LDMX4(a[0], a[1], a[2], a[3], ab + mt * 16 * GST * 2 + kk * 32);
                #pragma unroll
                for (int nt = 0; nt < 4; nt++) mma16(acc[mt][nt], a, bf[nt]);
            }
        }
    }

    #pragma unroll
    for (int mt = 0; mt < 4; mt++) {
        const int m = m0 + wm * 64 + mt * 16 + g;
        #pragma unroll
        for (int nt = 0; nt < 4; nt++) {
            const int n = n0 + wn * 32 + nt * 8 + 2 * tg;
            store2(C + (size_t)m * N + n,       acc[mt][nt][0], acc[mt][nt][1]);
            store2(C + (size_t)(m + 8) * N + n, acc[mt][nt][2], acc[mt][nt][3]);
        }
    }
}

// Kernel 3: q/k LN + RoPE (table) + transpose; reads fp16 qkv.
__global__ void __launch_bounds__(256) qk_rope_kernel(
    const float* __restrict__ q_ln_w, const float* __restrict__ k_ln_w)
{
    __shared__ float sm[D];
    __shared__ float sbuf[8];
    const int t = blockIdx.x, tid = threadIdx.x;
    const int b = t / L, l = t % L;

    // per-thread rope factors (4 consecutive dh in one head)
    const int i0 = (4 * tid) & 31;
    float4 rc0 = *(const float4*)(g_rope + l * 32 + i0);      // (cos,sin)(i0), (i0+1)
    float4 rc1 = *(const float4*)(g_rope + l * 32 + i0 + 2);  // (i0+2), (i0+3)
    const float cs[4] = {rc0.x, rc0.z, rc1.x, rc1.z};
    const float sn[4] = {rc0.y, rc0.w, rc1.y, rc1.w};

    #pragma unroll
    for (int seg = 0; seg < 2; seg++) {
        const __half* base = g_qkv_h + (size_t)t * (3 * D) + seg * D;
        const float* w    = (seg == 0) ? q_ln_w : k_ln_w;
        __half*      dst  = (seg == 0) ? g_qh   : g_kh;
        const float  osc  = (seg == 0) ? 0.125f : 1.0f;

        float2 x01 = __half22float2(*(const __half2*)(base + 4 * tid));
        float2 x23 = __half22float2(*(const __half2*)(base + 4 * tid + 2));
        float s  = x01.x + x01.y + x23.x + x23.y;
        float ss = fmaf(x01.x, x01.x, fmaf(x01.y, x01.y,
                   fmaf(x23.x, x23.x, x23.y * x23.y)));
        s  = block_reduce_sum_256(s,  sbuf);
        ss = block_reduce_sum_256(ss, sbuf);
        const float mu = s * (1.0f / D);
        const float rs = rsqrtf(ss * (1.0f / D) - mu * mu + EPS);

        const float4 wv = *(const float4*)(w + 4 * tid);
        sm[4 * tid + 0] = (x01.x - mu) * rs * wv.x;
        sm[4 * tid + 1] = (x01.y - mu) * rs * wv.y;
        sm[4 * tid + 2] = (x23.x - mu) * rs * wv.z;
        sm[4 * tid + 3] = (x23.y - mu) * rs * wv.w;
        __syncthreads();

        float out[4];
        #pragma unroll
        for (int c = 0; c < 4; c++) {
            int d  = 4 * tid + c;
            int dh = d & 63;
            if (dh < 32) out[c] = sm[d] * cs[c] - sm[d + 32] * sn[c];
            else         out[c] = sm[d] * cs[c] + sm[d - 32] * sn[c];
        }
        const int d0 = 4 * tid, head = d0 >> 6, dh0 = d0 & 63;
        __half* dp = dst + ((size_t)(b * H + head) * L + l) * DH + dh0;
        *(__half2*)(dp)     = __floats2half2_rn(out[0] * osc, out[1] * osc);
        *(__half2*)(dp + 2) = __floats2half2_rn(out[2] * osc, out[3] * osc);
        __syncthreads();
    }
    {
        const __half* base = g_qkv_h + (size_t)t * (3 * D) + 2 * D + 4 * tid;
        const int d0 = 4 * tid, head = d0 >> 6, dh0 = d0 & 63;
        __half* dp = g_vh + ((size_t)(b * H + head) * L + l) * DH + dh0;
        *(uint2*)dp = *(const uint2*)base;   // raw copy, already fp16
    }
}

// Kernel 4: fp16 flash attention v3 — P in registers, 3-stage KV ring.
constexpr int AST = 72;
constexpr int AKB = 64 * AST;
constexpr int ATTN_SMEM = (6 * AKB + 8 * 16 * AST) * 2;   // 73728 B
constexpr int NKT = L / 64;

__global__ void __launch_bounds__(256) attn_f16(__half* __restrict__ ctx)
{
    extern __shared__ __half hsm[];
    const uint32_t ks0 = smem_u32(hsm);
    const uint32_t vs0 = smem_u32(hsm + 3 * AKB);
    __half* Qstage = hsm + 6 * AKB + (threadIdx.x >> 5) * 16 * AST;
    const uint32_t qs0 = smem_u32(Qstage);

    const int tid  = threadIdx.x;
    const int lane = tid & 31;
    const int g    = lane >> 2;
    const int tg   = lane & 3;
    const int w    = tid >> 5;
    const int bh   = blockIdx.y;
    const int bb   = bh / H;
    const int hh   = bh % H;
    const int q0   = blockIdx.x * 128;

    const __half* Kg0 = g_kh + (size_t)bh * L * DH;
    const __half* Vg0 = g_vh + (size_t)bh * L * DH;

    auto stage_kv = [&](int slot, int kt) {
        const __half* Kg = Kg0 + (size_t)kt * 64 * DH;
        const __half* Vg = Vg0 + (size_t)kt * 64 * DH;
        const uint32_t kd = ks0 + slot * AKB * 2;
        const uint32_t vd = vs0 + slot * AKB * 2;
        #pragma unroll
        for (int r = 0; r < 2; r++) {
            int idx = tid + r * 256;
            int row = idx >> 3, col = (idx & 7) * 8;
            cp_async16(kd + (row * AST + col) * 2, Kg + row * DH + col);
            cp_async16(vd + (row * AST + col) * 2, Vg + row * DH + col);
        }
    };

    stage_kv(0, 0); CP_COMMIT();
    stage_kv(1, 1); CP_COMMIT();

    // stage this warp's Q (fp16, pre-scaled 1/8), hoist fragments
    uint32_t qa[4][4];
    {
        const __half* Qg = g_qh + ((size_t)bh * L + q0 + w * 16) * DH;
        #pragma unroll
        for (int r = 0; r < 4; r++) {
            int idx = lane + r * 32;
            int row = idx >> 3, col = (idx & 7) * 8;
            *(float4*)&Qstage[row * AST + col] = *(const float4*)(Qg + row * DH + col);
        }
        __syncwarp();
        const uint32_t qaddr = qs0 + ((lane & 15) * AST + (lane >> 4) * 8) * 2;
        #pragma unroll
        for (int ks = 0; ks < 4; ks++)
            LDMX4(qa[ks][0], qa[ks][1], qa[ks][2], qa[ks][3], qaddr + ks * 32);
    }

    float m0 = -1e30f, m1 = -1e30f, l0 = 0.0f, l1 = 0.0f;
    float o[8][4];
    #pragma unroll
    for (int nt = 0; nt < 8; nt++)
        #pragma unroll
        for (int i = 0; i < 4; i++) o[nt][i] = 0.0f;

    const uint32_t k_lane = (((lane & 7) + ((lane >> 4) << 3)) * AST +
                             ((lane >> 3) & 1) * 8) * 2;
    const uint32_t v_lane = (((lane & 7) + (((lane >> 3) & 1) << 3)) * AST +
                             ((lane >> 4) << 3)) * 2;

    for (int kt = 0; kt < NKT; kt++) {
        CP_WAIT1();
        __syncthreads();
        if (kt + 2 < NKT) stage_kv((kt + 2) % 3, kt + 2);
        CP_COMMIT();

        const uint32_t ksb = ks0 + (kt % 3) * AKB * 2;
        const uint32_t vsb = vs0 + (kt % 3) * AKB * 2;

        // S = (Q/8) K^T : 16x64
        float s[8][4];
        #pragma unroll
        for (int nt = 0; nt < 8; nt++)
            #pragma unroll
            for (int i = 0; i < 4; i++) s[nt][i] = 0.0f;

        #pragma unroll
        for (int ks = 0; ks < 4; ks++) {
            uint32_t bk[8][2];
            #pragma unroll
            for (int p = 0; p < 4; p++)
                LDMX4(bk[2*p][0], bk[2*p][1], bk[2*p+1][0], bk[2*p+1][1],
                      ksb + p * 16 * AST * 2 + ks * 32 + k_lane);
            #pragma unroll
            for (int nt = 0; nt < 8; nt++) mma16(s[nt], qa[ks], bk[nt]);
        }

        // online softmax in registers
        float mx0 = -1e30f, mx1 = -1e30f;
        #pragma unroll
        for (int nt = 0; nt < 8; nt++) {
            mx0 = fmaxf(mx0, fmaxf(s[nt][0], s[nt][1]));
            mx1 = fmaxf(mx1, fmaxf(s[nt][2], s[nt][3]));
        }
        mx0 = fmaxf(mx0, __shfl_xor_sync(0xffffffffu, mx0, 1));
        mx0 = fmaxf(mx0, __shfl_xor_sync(0xffffffffu, mx0, 2));
        mx1 = fmaxf(mx1, __shfl_xor_sync(0xffffffffu, mx1, 1));
        mx1 = fmaxf(mx1, __shfl_xor_sync(0xffffffffu, mx1, 2));
        const float nm0 = fmaxf(m0, mx0);
        const float nm1 = fmaxf(m1, mx1);

        // exp, pack P directly into A-fragment registers (C->A layout identity)
        float sum0 = 0.0f, sum1 = 0.0f;
        uint32_t ph[8][2];
        #pragma unroll
        for (int nt = 0; nt < 8; nt++) {
            ph[nt][0] = packh2(__expf(s[nt][0] - nm0), __expf(s[nt][1] - nm0));
            ph[nt][1] = packh2(__expf(s[nt][2] - nm1), __expf(s[nt][3] - nm1));
            float2 f01 = __half22float2(*(__half2*)&ph[nt][0]);
            float2 f23 = __half22float2(*(__half2*)&ph[nt][1]);
            sum0 += f01.x + f01.y;
            sum1 += f23.x + f23.y;
        }
        sum0 += __shfl_xor_sync(0xffffffffu, sum0, 1);
        sum0 += __shfl_xor_sync(0xffffffffu, sum0, 2);
        sum1 += __shfl_xor_sync(0xffffffffu, sum1, 1);
        sum1 += __shfl_xor_sync(0xffffffffu, sum1, 2);

        const float al0 = __expf(m0 - nm0);
        const float al1 = __expf(m1 - nm1);
        l0 = l0 * al0 + sum0;  m0 = nm0;
        l1 = l1 * al1 + sum1;  m1 = nm1;

        #pragma unroll
        for (int nt = 0; nt < 8; nt++) {
            o[nt][0] *= al0; o[nt][1] *= al0;
            o[nt][2] *= al1; o[nt][3] *= al1;
        }

        // O += P @ V, P from registers
        #pragma unroll
        for (int ks = 0; ks < 4; ks++) {
            uint32_t a[4] = {ph[2*ks][0], ph[2*ks][1], ph[2*ks+1][0], ph[2*ks+1][1]};
            #pragma unroll
            for (int p = 0; p < 4; p++) {
                uint32_t b0, b1, b2, b3;
                LDMX4T(b0, b1, b2, b3, vsb + (ks * 16) * AST * 2 + p * 32 + v_lane);
                uint32_t bA[2] = {b0, b1}, bB[2] = {b2, b3};
                mma16(o[2*p],     a, bA);
                mma16(o[2*p + 1], a, bB);
            }
        }
    }

    // epilogue -> fp16 ctx
    const float inv0 = 1.0f / l0;
    const float inv1 = 1.0f / l1;
    const int row0 = q0 + w * 16 + g;
    const int row1 = row0 + 8;
    #pragma unroll
    for (int nt = 0; nt < 8; nt++) {
        const int col = hh * DH + nt * 8 + 2 * tg;
        *(__half2*)(ctx + (size_t)(bb * L + row0) * D + col) =
            __floats2half2_rn(o[nt][0] * inv0, o[nt][1] * inv0);
        *(__half2*)(ctx + (size_t)(bb * L + row1) * D + col) =
            __floats2half2_rn(o[nt][2] * inv1, o[nt][3] * inv1);
    }
}

// Launch
extern "C" void kernel_launch(void* const* d_in, const int* in_sizes, int n_in,
                              void* d_out, int out_size)
{
    const float* x      = (const float*)d_in[0];
    const float* ln_w   = (const float*)d_in[1];
    const float* ln_b   = (const float*)d_in[2];
    const float* w_qkv  = (const float*)d_in[3];
    const float* q_ln_w = (const float*)d_in[4];
    const float* k_ln_w = (const float*)d_in[5];
    const float* w_out  = (const float*)d_in[6];
    float* out = (float*)d_out;

    __half *hh, *wq, *wo, *qkv, *ctx;
    cudaGetSymbolAddress((void**)&hh,  g_h_h);
    cudaGetSymbolAddress((void**)&wq,  g_wqkv_h);
    cudaGetSymbolAddress((void**)&wo,  g_wout_h);
    cudaGetSymbolAddress((void**)&qkv, g_qkv_h);
    cudaGetSymbolAddress((void**)&ctx, g_ctx_h);

    cudaFuncSetAttribute(gemm_nt_f16<__half>, cudaFuncAttributeMaxDynamicSharedMemorySize, GEMM_SMEM);
    cudaFuncSetAttribute(gemm_nt_f16<float>,  cudaFuncAttributeMaxDynamicSharedMemorySize, GEMM_SMEM);
    cudaFuncSetAttribute(attn_f16, cudaFuncAttributeMaxDynamicSharedMemorySize, ATTN_SMEM);

    prep_w<<<4096, 256>>>(w_qkv, w_out);
    rope_table<<<256, 256>>>();
    ln_kernel<<<BL, 256>>>(x, ln_w, ln_b);
    {
        dim3 grid(3 * D / 128, BL / 128);
        gemm_nt_f16<__half><<<grid, 256, GEMM_SMEM>>>(hh, wq, qkv, BL, 3 * D, D);
    }
    qk_rope_kernel<<<BL, 256>>>(q_ln_w, k_ln_w);
    {
        dim3 grid(L / 128, B * H);
        attn_f16<<<grid, 256, ATTN_SMEM>>>(ctx);
    }
    {
        dim3 grid(D / 128, BL / 128);
        gemm_nt_f16<float><<<grid, 256, GEMM_SMEM>>>(ctx, wo, out, BL, D, D);
    }
}

// round 9
// speedup vs baseline: 2.1447x; 1.0432x over previous
#include <cuda_runtime.h>
#include <cuda_fp16.h>
#include <math.h>
#include <stdint.h>

constexpr int B  = 2;
constexpr int L  = 2048;
constexpr int D  = 1024;
constexpr int H  = 16;
constexpr int DH = 64;
constexpr int BL = B * L;
constexpr float EPS = 1e-5f;
constexpr float LOG_ROPE_BASE = 9.210340371976184f;

// Scratch
__device__ __half g_h_h[BL * D];
__device__ __half g_wqkv_h[3 * D * D];
__device__ __half g_wout_h[D * D];
__device__ __half g_qkv_h[BL * 3 * D];
__device__ __half g_qh[BL * D];     // pre-scaled by 1/8
__device__ __half g_kh[BL * D];
__device__ __half g_vh[BL * D];
__device__ __half g_ctx_h[BL * D];
__device__ float2 g_rope[L * 32];

// Helpers
__device__ __forceinline__ uint32_t smem_u32(const void* p) {
    return (uint32_t)__cvta_generic_to_shared(p);
}
__device__ __forceinline__ void cp_async16(uint32_t dst, const void* src) {
    asm volatile("cp.async.cg.shared.global [%0], [%1], 16;" :: "r"(dst), "l"(src));
}
#define CP_COMMIT() asm volatile("cp.async.commit_group;")
#define CP_WAIT1()  asm volatile("cp.async.wait_group 1;")
#define LDMX4(r0,r1,r2,r3,addr) \
    asm volatile("ldmatrix.sync.aligned.m8n8.x4.shared.b16 {%0,%1,%2,%3},[%4];" \
                 : "=r"(r0),"=r"(r1),"=r"(r2),"=r"(r3) : "r"(addr))
#define LDMX4T(r0,r1,r2,r3,addr) \
    asm volatile("ldmatrix.sync.aligned.m8n8.x4.trans.shared.b16 {%0,%1,%2,%3},[%4];" \
                 : "=r"(r0),"=r"(r1),"=r"(r2),"=r"(r3) : "r"(addr))

__device__ __forceinline__ void mma16(float* c, const uint32_t* a, const uint32_t* b) {
    asm volatile(
        "mma.sync.aligned.m16n8k16.row.col.f32.f16.f16.f32 "
        "{%0,%1,%2,%3},{%4,%5,%6,%7},{%8,%9},{%0,%1,%2,%3};"
        : "+f"(c[0]), "+f"(c[1]), "+f"(c[2]), "+f"(c[3])
        : "r"(a[0]), "r"(a[1]), "r"(a[2]), "r"(a[3]), "r"(b[0]), "r"(b[1]));
}

__device__ __forceinline__ uint32_t packh2(float a, float b) {
    __half2 h = __floats2half2_rn(a, b);
    return *(uint32_t*)&h;
}

__device__ __forceinline__ float block_reduce_sum_256(float v, float* sbuf) {
    int tid = threadIdx.x;
    #pragma unroll
    for (int o = 16; o > 0; o >>= 1) v += __shfl_xor_sync(0xffffffffu, v, o);
    if ((tid & 31) == 0) sbuf[tid >> 5] = v;
    __syncthreads();
    if (tid < 8) {
        float w = sbuf[tid];
        #pragma unroll
        for (int o = 4; o > 0; o >>= 1) w += __shfl_xor_sync(0xffu, w, o);
        if (tid == 0) sbuf[0] = w;
    }
    __syncthreads();
    float r = sbuf[0];
    __syncthreads();
    return r;
}

// Kernel 0: weights -> fp16, plus RoPE angle table (merged)
__global__ void __launch_bounds__(256) prep_all(
    const float* __restrict__ wq, const float* __restrict__ wo)
{
    const int bid = blockIdx.x;
    if (bid < 4096) {
        const size_t i4 = ((size_t)bid * 256 + threadIdx.x) * 4;
        const size_t n1 = (size_t)3 * D * D;
        if (i4 < n1) {
            float4 v = *(const float4*)(wq + i4);
            *(__half2*)(g_wqkv_h + i4)     = __floats2half2_rn(v.x, v.y);
            *(__half2*)(g_wqkv_h + i4 + 2) = __floats2half2_rn(v.z, v.w);
        } else {
            size_t j = i4 - n1;
            float4 v = *(const float4*)(wo + j);
            *(__half2*)(g_wout_h + j)     = __floats2half2_rn(v.x, v.y);
            *(__half2*)(g_wout_h + j + 2) = __floats2half2_rn(v.z, v.w);
        }
    } else {
        const int idx = (bid - 4096) * 256 + threadIdx.x;   // 0..65535
        const int l = idx >> 5;
        const int i = idx & 31;
        float inv_freq = expf(-(float)(2 * i) * (1.0f / 64.0f) * LOG_ROPE_BASE);
        float sn, cs;
        sincosf((float)l * inv_freq, &sn, &cs);
        g_rope[idx] = make_float2(cs, sn);
    }
}

// Kernel 1: LayerNorm -> fp16 hidden
__global__ void __launch_bounds__(256) ln_kernel(
    const float* __restrict__ x, const float* __restrict__ w,
    const float* __restrict__ bias)
{
    __shared__ float sbuf[8];
    const int t = blockIdx.x, tid = threadIdx.x;
    const float4 xv = *(const float4*)(x + (size_t)t * D + 4 * tid);
    float s  = xv.x + xv.y + xv.z + xv.w;
    float ss = fmaf(xv.x, xv.x, fmaf(xv.y, xv.y, fmaf(xv.z, xv.z, xv.w * xv.w)));
    s  = block_reduce_sum_256(s,  sbuf);
    ss = block_reduce_sum_256(ss, sbuf);
    const float mu = s * (1.0f / D);
    const float rs = rsqrtf(ss * (1.0f / D) - mu * mu + EPS);
    const float4 wv = *(const float4*)(w    + 4 * tid);
    const float4 bv = *(const float4*)(bias + 4 * tid);
    __half* dst = g_h_h + (size_t)t * D + 4 * tid;
    *(__half2*)(dst)     = __floats2half2_rn((xv.x - mu) * rs * wv.x + bv.x,
                                             (xv.y - mu) * rs * wv.y + bv.y);
    *(__half2*)(dst + 2) = __floats2half2_rn((xv.z - mu) * rs * wv.z + bv.z,
                                             (xv.w - mu) * rs * wv.w + bv.w);
}

// ---------------------------------------------------------------------------
// Kernel 2/5: fp16 GEMM-NT, K-chunk 64, 3-stage cp.async ring.
// ---------------------------------------------------------------------------
constexpr int GST  = 72;                    // halves per smem row (144B)
constexpr int GBUF = 128 * GST * 2;         // bytes per stage per matrix (18432)
constexpr int GEMM_SMEM = 6 * GBUF;         // 110592 B

__device__ __forceinline__ void store2(float* p, float a, float b) {
    *(float2*)p = make_float2(a, b);
}
__device__ __forceinline__ void store2(__half* p, float a, float b) {
    *(__half2*)p = __floats2half2_rn(a, b);
}

template <typename TOut>
__global__ void __launch_bounds__(256) gemm_nt_f16(
    const __half* __restrict__ A, const __half* __restrict__ Bm,
    TOut* __restrict__ C, int M, int N, int K)
{
    extern __shared__ __half gsm[];
    const uint32_t as0 = smem_u32(gsm);
    const uint32_t bs0 = smem_u32(gsm + 3 * 128 * GST);

    const int tid  = threadIdx.x;
    const int lane = tid & 31;
    const int g    = lane >> 2;
    const int tg   = lane & 3;
    const int wid  = tid >> 5;
    const int wm   = wid >> 2;
    const int wn   = wid & 3;
    const int m0   = blockIdx.y * 128;
    const int n0   = blockIdx.x * 128;

    float acc[4][4][4];
    #pragma unroll
    for (int mt = 0; mt < 4; mt++)
        #pragma unroll
        for (int nt = 0; nt < 4; nt++)
            #pragma unroll
            for (int i = 0; i < 4; i++) acc[mt][nt][i] = 0.0f;

    auto stage = [&](int s, int k0) {
        #pragma unroll
        for (int r = 0; r < 4; r++) {
            int qid = tid + r * 256;         // 0..1023
            int row = qid >> 3;              // 0..127
            int cq  = (qid & 7) * 8;         // 0..56
            cp_async16(as0 + s * GBUF + (row * GST + cq) * 2,
                       A + (size_t)(m0 + row) * K + k0 + cq);
            cp_async16(bs0 + s * GBUF + (row * GST + cq) * 2,
                       Bm + (size_t)(n0 + row) * K + k0 + cq);
        }
    };
    stage(0, 0);  CP_COMMIT();
    stage(1, 64); CP_COMMIT();

    const uint32_t a_lane = ((lane & 15) * GST + (lane >> 4) * 8) * 2;
    const uint32_t b_lane = ((((lane >> 4) << 3) + (lane & 7)) * GST +
                             ((lane >> 3) & 1) * 8) * 2;

    const int NIT = K / 64;
    for (int kt = 0; kt < NIT; kt++) {
        CP_WAIT1();
        __syncthreads();
        if (kt + 2 < NIT) stage((kt + 2) % 3, (kt + 2) * 64);
        CP_COMMIT();

        const uint32_t ab = as0 + (kt % 3) * GBUF + (wm * 64) * GST * 2 + a_lane;
        const uint32_t bb = bs0 + (kt % 3) * GBUF + (wn * 32) * GST * 2 + b_lane;

        #pragma unroll
        for (int kk = 0; kk < 4; kk++) {
            uint32_t bf[4][2];
            #pragma unroll
            for (int p = 0; p < 2; p++)
                LDMX4(bf[2*p][0], bf[2*p][1], bf[2*p+1][0], bf[2*p+1][1],
                      bb + p * 16 * GST * 2 + kk * 32);
            #pragma unroll
            for (int mt = 0; mt < 4; mt++) {
                uint32_t a[4];
                LDMX4(a[0], a[1], a[2], a[3], ab + mt * 16 * GST * 2 + kk * 32);
                #pragma unroll
                for (int nt = 0; nt < 4; nt++) mma16(acc[mt][nt], a, bf[nt]);
            }
        }
    }

    #pragma unroll
    for (int mt = 0; mt < 4; mt++) {
        const int m = m0 + wm * 64 + mt * 16 + g;
        #pragma unroll
        for (int nt = 0; nt < 4; nt++) {
            const int n = n0 + wn * 32 + nt * 8 + 2 * tg;
            store2(C + (size_t)m * N + n,       acc[mt][nt][0], acc[mt][nt][1]);
            store2(C + (size_t)(m + 8) * N + n, acc[mt][nt][2], acc[mt][nt][3]);
        }
    }
}

// Kernel 3: q/k LN + RoPE (table) + transpose; reads fp16 qkv.
__global__ void __launch_bounds__(256) qk_rope_kernel(
    const float* __restrict__ q_ln_w, const float* __restrict__ k_ln_w)
{
    __shared__ float sm[D];
    __shared__ float sbuf[8];
    const int t = blockIdx.x, tid = threadIdx.x;
    const int b = t / L, l = t % L;

    const int i0 = (4 * tid) & 31;
    float4 rc0 = *(const float4*)(g_rope + l * 32 + i0);
    float4 rc1 = *(const float4*)(g_rope + l * 32 + i0 + 2);
    const float cs[4] = {rc0.x, rc0.z, rc1.x, rc1.z};
    const float sn[4] = {rc0.y, rc0.w, rc1.y, rc1.w};

    #pragma unroll
    for (int seg = 0; seg < 2; seg++) {
        const __half* base = g_qkv_h + (size_t)t * (3 * D) + seg * D;
        const float* w    = (seg == 0) ? q_ln_w : k_ln_w;
        __half*      dst  = (seg == 0) ? g_qh   : g_kh;
        const float  osc  = (seg == 0) ? 0.125f : 1.0f;

        float2 x01 = __half22float2(*(const __half2*)(base + 4 * tid));
        float2 x23 = __half22float2(*(const __half2*)(base + 4 * tid + 2));
        float s  = x01.x + x01.y + x23.x + x23.y;
        float ss = fmaf(x01.x, x01.x, fmaf(x01.y, x01.y,
                   fmaf(x23.x, x23.x, x23.y * x23.y)));
        s  = block_reduce_sum_256(s,  sbuf);
        ss = block_reduce_sum_256(ss, sbuf);
        const float mu = s * (1.0f / D);
        const float rs = rsqrtf(ss * (1.0f / D) - mu * mu + EPS);

        const float4 wv = *(const float4*)(w + 4 * tid);
        sm[4 * tid + 0] = (x01.x - mu) * rs * wv.x;
        sm[4 * tid + 1] = (x01.y - mu) * rs * wv.y;
        sm[4 * tid + 2] = (x23.x - mu) * rs * wv.z;
        sm[4 * tid + 3] = (x23.y - mu) * rs * wv.w;
        __syncthreads();

        float out[4];
        #pragma unroll
        for (int c = 0; c < 4; c++) {
            int d  = 4 * tid + c;
            int dh = d & 63;
            if (dh < 32) out[c] = sm[d] * cs[c] - sm[d + 32] * sn[c];
            else         out[c] = sm[d] * cs[c] + sm[d - 32] * sn[c];
        }
        const int d0 = 4 * tid, head = d0 >> 6, dh0 = d0 & 63;
        __half* dp = dst + ((size_t)(b * H + head) * L + l) * DH + dh0;
        *(__half2*)(dp)     = __floats2half2_rn(out[0] * osc, out[1] * osc);
        *(__half2*)(dp + 2) = __floats2half2_rn(out[2] * osc, out[3] * osc);
        __syncthreads();
    }
    {
        const __half* base = g_qkv_h + (size_t)t * (3 * D) + 2 * D + 4 * tid;
        const int d0 = 4 * tid, head = d0 >> 6, dh0 = d0 & 63;
        __half* dp = g_vh + ((size_t)(b * H + head) * L + l) * DH + dh0;
        *(uint2*)dp = *(const uint2*)base;
    }
}

// Kernel 4: fp16 flash attention (R7 design: P in registers, 3-stage KV ring)
constexpr int AST = 72;
constexpr int AKB = 64 * AST;
constexpr int ATTN_SMEM = (6 * AKB + 8 * 16 * AST) * 2;
constexpr int NKT = L / 64;

__global__ void __launch_bounds__(256) attn_f16(__half* __restrict__ ctx)
{
    extern __shared__ __half hsm[];
    const uint32_t ks0 = smem_u32(hsm);
    const uint32_t vs0 = smem_u32(hsm + 3 * AKB);
    __half* Qstage = hsm + 6 * AKB + (threadIdx.x >> 5) * 16 * AST;
    const uint32_t qs0 = smem_u32(Qstage);

    const int tid  = threadIdx.x;
    const int lane = tid & 31;
    const int g    = lane >> 2;
    const int tg   = lane & 3;
    const int w    = tid >> 5;
    const int bh   = blockIdx.y;
    const int bb   = bh / H;
    const int hh   = bh % H;
    const int q0   = blockIdx.x * 128;

    const __half* Kg0 = g_kh + (size_t)bh * L * DH;
    const __half* Vg0 = g_vh + (size_t)bh * L * DH;

    auto stage_kv = [&](int slot, int kt) {
        const __half* Kg = Kg0 + (size_t)kt * 64 * DH;
        const __half* Vg = Vg0 + (size_t)kt * 64 * DH;
        const uint32_t kd = ks0 + slot * AKB * 2;
        const uint32_t vd = vs0 + slot * AKB * 2;
        #pragma unroll
        for (int r = 0; r < 2; r++) {
            int idx = tid + r * 256;
            int row = idx >> 3, col = (idx & 7) * 8;
            cp_async16(kd + (row * AST + col) * 2, Kg + row * DH + col);
            cp_async16(vd + (row * AST + col) * 2, Vg + row * DH + col);
        }
    };

    stage_kv(0, 0); CP_COMMIT();
    stage_kv(1, 1); CP_COMMIT();

    uint32_t qa[4][4];
    {
        const __half* Qg = g_qh + ((size_t)bh * L + q0 + w * 16) * DH;
        #pragma unroll
        for (int r = 0; r < 4; r++) {
            int idx = lane + r * 32;
            int row = idx >> 3, col = (idx & 7) * 8;
            *(float4*)&Qstage[row * AST + col] = *(const float4*)(Qg + row * DH + col);
        }
        __syncwarp();
        const uint32_t qaddr = qs0 + ((lane & 15) * AST + (lane >> 4) * 8) * 2;
        #pragma unroll
        for (int ks = 0; ks < 4; ks++)
            LDMX4(qa[ks][0], qa[ks][1], qa[ks][2], qa[ks][3], qaddr + ks * 32);
    }

    float m0 = -1e30f, m1 = -1e30f, l0 = 0.0f, l1 = 0.0f;
    float o[8][4];
    #pragma unroll
    for (int nt = 0; nt < 8; nt++)
        #pragma unroll
        for (int i = 0; i < 4; i++) o[nt][i] = 0.0f;

    const uint32_t k_lane = (((lane & 7) + ((lane >> 4) << 3)) * AST +
                             ((lane >> 3) & 1) * 8) * 2;
    const uint32_t v_lane = (((lane & 7) + (((lane >> 3) & 1) << 3)) * AST +
                             ((lane >> 4) << 3)) * 2;

    for (int kt = 0; kt < NKT; kt++) {
        CP_WAIT1();
        __syncthreads();
        if (kt + 2 < NKT) stage_kv((kt + 2) % 3, kt + 2);
        CP_COMMIT();

        const uint32_t ksb = ks0 + (kt % 3) * AKB * 2;
        const uint32_t vsb = vs0 + (kt % 3) * AKB * 2;

        float s[8][4];
        #pragma unroll
        for (int nt = 0; nt < 8; nt++)
            #pragma unroll
            for (int i = 0; i < 4; i++) s[nt][i] = 0.0f;

        #pragma unroll
        for (int ks = 0; ks < 4; ks++) {
            uint32_t bk[8][2];
            #pragma unroll
            for (int p = 0; p < 4; p++)
                LDMX4(bk[2*p][0], bk[2*p][1], bk[2*p+1][0], bk[2*p+1][1],
                      ksb + p * 16 * AST * 2 + ks * 32 + k_lane);
            #pragma unroll
            for (int nt = 0; nt < 8; nt++) mma16(s[nt], qa[ks], bk[nt]);
        }

        float mx0 = -1e30f, mx1 = -1e30f;
        #pragma unroll
        for (int nt = 0; nt < 8; nt++) {
            mx0 = fmaxf(mx0, fmaxf(s[nt][0], s[nt][1]));
            mx1 = fmaxf(mx1, fmaxf(s[nt][2], s[nt][3]));
        }
        mx0 = fmaxf(mx0, __shfl_xor_sync(0xffffffffu, mx0, 1));
        mx0 = fmaxf(mx0, __shfl_xor_sync(0xffffffffu, mx0, 2));
        mx1 = fmaxf(mx1, __shfl_xor_sync(0xffffffffu, mx1, 1));
        mx1 = fmaxf(mx1, __shfl_xor_sync(0xffffffffu, mx1, 2));
        const float nm0 = fmaxf(m0, mx0);
        const float nm1 = fmaxf(m1, mx1);

        float sum0 = 0.0f, sum1 = 0.0f;
        uint32_t ph[8][2];
        #pragma unroll
        for (int nt = 0; nt < 8; nt++) {
            ph[nt][0] = packh2(__expf(s[nt][0] - nm0), __expf(s[nt][1] - nm0));
            ph[nt][1] = packh2(__expf(s[nt][2] - nm1), __expf(s[nt][3] - nm1));
            float2 f01 = __half22float2(*(__half2*)&ph[nt][0]);
            float2 f23 = __half22float2(*(__half2*)&ph[nt][1]);
            sum0 += f01.x + f01.y;
            sum1 += f23.x + f23.y;
        }
        sum0 += __shfl_xor_sync(0xffffffffu, sum0, 1);
        sum0 += __shfl_xor_sync(0xffffffffu, sum0, 2);
        sum1 += __shfl_xor_sync(0xffffffffu, sum1, 1);
        sum1 += __shfl_xor_sync(0xffffffffu, sum1, 2);

        const float al0 = __expf(m0 - nm0);
        const float al1 = __expf(m1 - nm1);
        l0 = l0 * al0 + sum0;  m0 = nm0;
        l1 = l1 * al1 + sum1;  m1 = nm1;

        #pragma unroll
        for (int nt = 0; nt < 8; nt++) {
            o[nt][0] *= al0; o[nt][1] *= al0;
            o[nt][2] *= al1; o[nt][3] *= al1;
        }

        #pragma unroll
        for (int ks = 0; ks < 4; ks++) {
            uint32_t a[4] = {ph[2*ks][0], ph[2*ks][1], ph[2*ks+1][0], ph[2*ks+1][1]};
            #pragma unroll
            for (int p = 0; p < 4; p++) {
                uint32_t b0, b1, b2, b3;
                LDMX4T(b0, b1, b2, b3, vsb + (ks * 16) * AST * 2 + p * 32 + v_lane);
                uint32_t bA[2] = {b0, b1}, bB[2] = {b2, b3};
                mma16(o[2*p],     a, bA);
                mma16(o[2*p + 1], a, bB);
            }
        }
    }

    const float inv0 = 1.0f / l0;
    const float inv1 = 1.0f / l1;
    const int row0 = q0 + w * 16 + g;
    const int row1 = row0 + 8;
    #pragma unroll
    for (int nt = 0; nt < 8; nt++) {
        const int col = hh * DH + nt * 8 + 2 * tg;
        *(__half2*)(ctx + (size_t)(bb * L + row0) * D + col) =
            __floats2half2_rn(o[nt][0] * inv0, o[nt][1] * inv0);
        *(__half2*)(ctx + (size_t)(bb * L + row1) * D + col) =
            __floats2half2_rn(o[nt][2] * inv1, o[nt][3] * inv1);
    }
}

// Launch
extern "C" void kernel_launch(void* const* d_in, const int* in_sizes, int n_in,
                              void* d_out, int out_size)
{
    const float* x      = (const float*)d_in[0];
    const float* ln_w   = (const float*)d_in[1];
    const float* ln_b   = (const float*)d_in[2];
    const float* w_qkv  = (const float*)d_in[3];
    const float* q_ln_w = (const float*)d_in[4];
    const float* k_ln_w = (const float*)d_in[5];
    const float* w_out  = (const float*)d_in[6];
    float* out = (float*)d_out;

    __half *hh, *wq, *wo, *qkv, *ctx;
    cudaGetSymbolAddress((void**)&hh,  g_h_h);
    cudaGetSymbolAddress((void**)&wq,  g_wqkv_h);
    cudaGetSymbolAddress((void**)&wo,  g_wout_h);
    cudaGetSymbolAddress((void**)&qkv, g_qkv_h);
    cudaGetSymbolAddress((void**)&ctx, g_ctx_h);

    cudaFuncSetAttribute(gemm_nt_f16<__half>, cudaFuncAttributeMaxDynamicSharedMemorySize, GEMM_SMEM);
    cudaFuncSetAttribute(gemm_nt_f16<float>,  cudaFuncAttributeMaxDynamicSharedMemorySize, GEMM_SMEM);
    cudaFuncSetAttribute(attn_f16, cudaFuncAttributeMaxDynamicSharedMemorySize, ATTN_SMEM);

    prep_all<<<4096 + 256, 256>>>(w_qkv, w_out);
    ln_kernel<<<BL, 256>>>(x, ln_w, ln_b);
    {
        dim3 grid(3 * D / 128, BL / 128);
        gemm_nt_f16<__half><<<grid, 256, GEMM_SMEM>>>(hh, wq, qkv, BL, 3 * D, D);
    }
    qk_rope_kernel<<<BL, 256>>>(q_ln_w, k_ln_w);
    {
        dim3 grid(L / 128, B * H);
        attn_f16<<<grid, 256, ATTN_SMEM>>>(ctx);
    }
    {
        dim3 grid(D / 128, BL / 128);
        gemm_nt_f16<float><<<grid, 256, GEMM_SMEM>>>(ctx, wo, out, BL, D, D);
    }
}

// round 10
// speedup vs baseline: 2.2159x; 1.0332x over previous
#include <cuda_runtime.h>
#include <cuda_fp16.h>
#include <math.h>
#include <stdint.h>

constexpr int B  = 2;
constexpr int L  = 2048;
constexpr int D  = 1024;
constexpr int H  = 16;
constexpr int DH = 64;
constexpr int BL = B * L;
constexpr float EPS = 1e-5f;
constexpr float LOG_ROPE_BASE = 9.210340371976184f;

// Scratch
__device__ __half g_h_h[BL * D];
__device__ __half g_wqkv_h[3 * D * D];
__device__ __half g_wout_h[D * D];
__device__ __half g_qkv_h[BL * 3 * D];
__device__ __half g_qh[BL * D];     // pre-scaled by 1/8
__device__ __half g_kh[BL * D];
__device__ __half g_vh[BL * D];
__device__ __half g_ctx_h[BL * D];
__device__ float2 g_rope[L * 32];

// Helpers
__device__ __forceinline__ uint32_t smem_u32(const void* p) {
    return (uint32_t)__cvta_generic_to_shared(p);
}
__device__ __forceinline__ void cp_async16(uint32_t dst, const void* src) {
    asm volatile("cp.async.cg.shared.global [%0], [%1], 16;" :: "r"(dst), "l"(src));
}
#define CP_COMMIT() asm volatile("cp.async.commit_group;")
#define CP_WAIT1()  asm volatile("cp.async.wait_group 1;")
#define LDMX4(r0,r1,r2,r3,addr) \
    asm volatile("ldmatrix.sync.aligned.m8n8.x4.shared.b16 {%0,%1,%2,%3},[%4];" \
                 : "=r"(r0),"=r"(r1),"=r"(r2),"=r"(r3) : "r"(addr))
#define LDMX4T(r0,r1,r2,r3,addr) \
    asm volatile("ldmatrix.sync.aligned.m8n8.x4.trans.shared.b16 {%0,%1,%2,%3},[%4];" \
                 : "=r"(r0),"=r"(r1),"=r"(r2),"=r"(r3) : "r"(addr))

__device__ __forceinline__ void mma16(float* c, const uint32_t* a, const uint32_t* b) {
    asm volatile(
        "mma.sync.aligned.m16n8k16.row.col.f32.f16.f16.f32 "
        "{%0,%1,%2,%3},{%4,%5,%6,%7},{%8,%9},{%0,%1,%2,%3};"
        : "+f"(c[0]), "+f"(c[1]), "+f"(c[2]), "+f"(c[3])
        : "r"(a[0]), "r"(a[1]), "r"(a[2]), "r"(a[3]), "r"(b[0]), "r"(b[1]));
}

__device__ __forceinline__ uint32_t packh2(float a, float b) {
    __half2 h = __floats2half2_rn(a, b);
    return *(uint32_t*)&h;
}

__device__ __forceinline__ float block_reduce_sum_256(float v, float* sbuf) {
    int tid = threadIdx.x;
    #pragma unroll
    for (int o = 16; o > 0; o >>= 1) v += __shfl_xor_sync(0xffffffffu, v, o);
    if ((tid & 31) == 0) sbuf[tid >> 5] = v;
    __syncthreads();
    if (tid < 8) {
        float w = sbuf[tid];
        #pragma unroll
        for (int o = 4; o > 0; o >>= 1) w += __shfl_xor_sync(0xffu, w, o);
        if (tid == 0) sbuf[0] = w;
    }
    __syncthreads();
    float r = sbuf[0];
    __syncthreads();
    return r;
}

// Reduce 4 values in one barrier pair (256 threads)
__device__ __forceinline__ float4 block_reduce_sum4(float4 v) {
    __shared__ float4 sb[8];
    const int tid = threadIdx.x;
    #pragma unroll
    for (int o = 16; o > 0; o >>= 1) {
        v.x += __shfl_xor_sync(0xffffffffu, v.x, o);
        v.y += __shfl_xor_sync(0xffffffffu, v.y, o);
        v.z += __shfl_xor_sync(0xffffffffu, v.z, o);
        v.w += __shfl_xor_sync(0xffffffffu, v.w, o);
    }
    if ((tid & 31) == 0) sb[tid >> 5] = v;
    __syncthreads();
    if (tid < 8) {
        float4 w = sb[tid];
        #pragma unroll
        for (int o = 4; o > 0; o >>= 1) {
            w.x += __shfl_xor_sync(0xffu, w.x, o);
            w.y += __shfl_xor_sync(0xffu, w.y, o);
            w.z += __shfl_xor_sync(0xffu, w.z, o);
            w.w += __shfl_xor_sync(0xffu, w.w, o);
        }
        if (tid == 0) sb[0] = w;
    }
    __syncthreads();
    return sb[0];
}

// ---------------------------------------------------------------------------
// Kernel 1 (merged): blocks [0,4096) LayerNorm -> fp16 hidden;
// [4096,8192) weights -> fp16; [8192,8448) RoPE table.
// ---------------------------------------------------------------------------
__global__ void __launch_bounds__(256) ln_prep_kernel(
    const float* __restrict__ x, const float* __restrict__ w,
    const float* __restrict__ bias,
    const float* __restrict__ wq, const float* __restrict__ wo)
{
    const int bid = blockIdx.x;
    const int tid = threadIdx.x;
    if (bid < BL) {
        __shared__ float sbuf[8];
        const int t = bid;
        const float4 xv = *(const float4*)(x + (size_t)t * D + 4 * tid);
        float s  = xv.x + xv.y + xv.z + xv.w;
        float ss = fmaf(xv.x, xv.x, fmaf(xv.y, xv.y, fmaf(xv.z, xv.z, xv.w * xv.w)));
        s  = block_reduce_sum_256(s,  sbuf);
        ss = block_reduce_sum_256(ss, sbuf);
        const float mu = s * (1.0f / D);
        const float rs = rsqrtf(ss * (1.0f / D) - mu * mu + EPS);
        const float4 wv = *(const float4*)(w    + 4 * tid);
        const float4 bv = *(const float4*)(bias + 4 * tid);
        __half* dst = g_h_h + (size_t)t * D + 4 * tid;
        *(__half2*)(dst)     = __floats2half2_rn((xv.x - mu) * rs * wv.x + bv.x,
                                                 (xv.y - mu) * rs * wv.y + bv.y);
        *(__half2*)(dst + 2) = __floats2half2_rn((xv.z - mu) * rs * wv.z + bv.z,
                                                 (xv.w - mu) * rs * wv.w + bv.w);
    } else if (bid < BL + 4096) {
        const size_t i4 = ((size_t)(bid - BL) * 256 + tid) * 4;
        const size_t n1 = (size_t)3 * D * D;
        if (i4 < n1) {
            float4 v = *(const float4*)(wq + i4);
            *(__half2*)(g_wqkv_h + i4)     = __floats2half2_rn(v.x, v.y);
            *(__half2*)(g_wqkv_h + i4 + 2) = __floats2half2_rn(v.z, v.w);
        } else {
            size_t j = i4 - n1;
            float4 v = *(const float4*)(wo + j);
            *(__half2*)(g_wout_h + j)     = __floats2half2_rn(v.x, v.y);
            *(__half2*)(g_wout_h + j + 2) = __floats2half2_rn(v.z, v.w);
        }
    } else {
        const int idx = (bid - BL - 4096) * 256 + tid;   // 0..65535
        const int l = idx >> 5;
        const int i = idx & 31;
        float inv_freq = expf(-(float)(2 * i) * (1.0f / 64.0f) * LOG_ROPE_BASE);
        float sn, cs;
        sincosf((float)l * inv_freq, &sn, &cs);
        g_rope[idx] = make_float2(cs, sn);
    }
}

// ---------------------------------------------------------------------------
// Kernel 2/5: fp16 GEMM-NT, K-chunk 64, 3-stage cp.async ring (R9 design).
// ---------------------------------------------------------------------------
constexpr int GST  = 72;
constexpr int GBUF = 128 * GST * 2;
constexpr int GEMM_SMEM = 6 * GBUF;

__device__ __forceinline__ void store2(float* p, float a, float b) {
    *(float2*)p = make_float2(a, b);
}
__device__ __forceinline__ void store2(__half* p, float a, float b) {
    *(__half2*)p = __floats2half2_rn(a, b);
}

template <typename TOut>
__global__ void __launch_bounds__(256) gemm_nt_f16(
    const __half* __restrict__ A, const __half* __restrict__ Bm,
    TOut* __restrict__ C, int M, int N, int K)
{
    extern __shared__ __half gsm[];
    const uint32_t as0 = smem_u32(gsm);
    const uint32_t bs0 = smem_u32(gsm + 3 * 128 * GST);

    const int tid  = threadIdx.x;
    const int lane = tid & 31;
    const int g    = lane >> 2;
    const int tg   = lane & 3;
    const int wid  = tid >> 5;
    const int wm   = wid >> 2;
    const int wn   = wid & 3;
    const int m0   = blockIdx.y * 128;
    const int n0   = blockIdx.x * 128;

    float acc[4][4][4];
    #pragma unroll
    for (int mt = 0; mt < 4; mt++)
        #pragma unroll
        for (int nt = 0; nt < 4; nt++)
            #pragma unroll
            for (int i = 0; i < 4; i++) acc[mt][nt][i] = 0.0f;

    auto stage = [&](int s, int k0) {
        #pragma unroll
        for (int r = 0; r < 4; r++) {
            int qid = tid + r * 256;
            int row = qid >> 3;
            int cq  = (qid & 7) * 8;
            cp_async16(as0 + s * GBUF + (row * GST + cq) * 2,
                       A + (size_t)(m0 + row) * K + k0 + cq);
            cp_async16(bs0 + s * GBUF + (row * GST + cq) * 2,
                       Bm + (size_t)(n0 + row) * K + k0 + cq);
        }
    };
    stage(0, 0);  CP_COMMIT();
    stage(1, 64); CP_COMMIT();

    const uint32_t a_lane = ((lane & 15) * GST + (lane >> 4) * 8) * 2;
    const uint32_t b_lane = ((((lane >> 4) << 3) + (lane & 7)) * GST +
                             ((lane >> 3) & 1) * 8) * 2;

    const int NIT = K / 64;
    for (int kt = 0; kt < NIT; kt++) {
        CP_WAIT1();
        __syncthreads();
        if (kt + 2 < NIT) stage((kt + 2) % 3, (kt + 2) * 64);
        CP_COMMIT();

        const uint32_t ab = as0 + (kt % 3) * GBUF + (wm * 64) * GST * 2 + a_lane;
        const uint32_t bb = bs0 + (kt % 3) * GBUF + (wn * 32) * GST * 2 + b_lane;

        #pragma unroll
        for (int kk = 0; kk < 4; kk++) {
            uint32_t bf[4][2];
            #pragma unroll
            for (int p = 0; p < 2; p++)
                LDMX4(bf[2*p][0], bf[2*p][1], bf[2*p+1][0], bf[2*p+1][1],
                      bb + p * 16 * GST * 2 + kk * 32);
            #pragma unroll
            for (int mt = 0; mt < 4; mt++) {
                uint32_t a[4];
                LDMX4(a[0], a[1], a[2], a[3], ab + mt * 16 * GST * 2 + kk * 32);
                #pragma unroll
                for (int nt = 0; nt < 4; nt++) mma16(acc[mt][nt], a, bf[nt]);
            }
        }
    }

    #pragma unroll
    for (int mt = 0; mt < 4; mt++) {
        const int m = m0 + wm * 64 + mt * 16 + g;
        #pragma unroll
        for (int nt = 0; nt < 4; nt++) {
            const int n = n0 + wn * 32 + nt * 8 + 2 * tg;
            store2(C + (size_t)m * N + n,       acc[mt][nt][0], acc[mt][nt][1]);
            store2(C + (size_t)(m + 8) * N + n, acc[mt][nt][2], acc[mt][nt][3]);
        }
    }
}

// ---------------------------------------------------------------------------
// Kernel 3: q/k LN + RoPE, shfl-based rotation, single fused reduction.
// Partner exchange: element d+-32 lives in thread tid^8 (4*(tid^8) = d+-32).
// ---------------------------------------------------------------------------
__global__ void __launch_bounds__(256) qk_rope_kernel(
    const float* __restrict__ q_ln_w, const float* __restrict__ k_ln_w)
{
    const int t = blockIdx.x, tid = threadIdx.x;
    const int b = t / L, l = t % L;

    // rope factors for this thread's 4 lanes
    const int i0 = (4 * tid) & 31;
    float4 rc0 = *(const float4*)(g_rope + l * 32 + i0);
    float4 rc1 = *(const float4*)(g_rope + l * 32 + i0 + 2);
    const float cs[4] = {rc0.x, rc0.z, rc1.x, rc1.z};
    const float sn[4] = {rc0.y, rc0.w, rc1.y, rc1.w};
    const float sgn = (tid & 8) ? 1.0f : -1.0f;

    // load q and k slices
    const __half* qb = g_qkv_h + (size_t)t * (3 * D) + 4 * tid;
    float2 q01 = __half22float2(*(const __half2*)(qb));
    float2 q23 = __half22float2(*(const __half2*)(qb + 2));
    float2 k01 = __half22float2(*(const __half2*)(qb + D));
    float2 k23 = __half22float2(*(const __half2*)(qb + D + 2));

    // fused reduction: {q_sum, q_ss, k_sum, k_ss}
    float4 r;
    r.x = q01.x + q01.y + q23.x + q23.y;
    r.y = fmaf(q01.x, q01.x, fmaf(q01.y, q01.y, fmaf(q23.x, q23.x, q23.y * q23.y)));
    r.z = k01.x + k01.y + k23.x + k23.y;
    r.w = fmaf(k01.x, k01.x, fmaf(k01.y, k01.y, fmaf(k23.x, k23.x, k23.y * k23.y)));
    r = block_reduce_sum4(r);

    const int d0 = 4 * tid, head = d0 >> 6, dh0 = d0 & 63;
    const size_t obase = ((size_t)(b * H + head) * L + l) * DH + dh0;

    // q segment
    {
        const float mu = r.x * (1.0f / D);
        const float rs = rsqrtf(r.y * (1.0f / D) - mu * mu + EPS);
        const float4 wv = *(const float4*)(q_ln_w + 4 * tid);
        float y[4] = {(q01.x - mu) * rs * wv.x, (q01.y - mu) * rs * wv.y,
                      (q23.x - mu) * rs * wv.z, (q23.y - mu) * rs * wv.w};
        float out[4];
        #pragma unroll
        for (int c = 0; c < 4; c++) {
            float p = __shfl_xor_sync(0xffffffffu, y[c], 8);
            out[c] = fmaf(sgn * p, sn[c], y[c] * cs[c]);
        }
        __half* dp = g_qh + obase;
        *(__half2*)(dp)     = __floats2half2_rn(out[0] * 0.125f, out[1] * 0.125f);
        *(__half2*)(dp + 2) = __floats2half2_rn(out[2] * 0.125f, out[3] * 0.125f);
    }
    // k segment
    {
        const float mu = r.z * (1.0f / D);
        const float rs = rsqrtf(r.w * (1.0f / D) - mu * mu + EPS);
        const float4 wv = *(const float4*)(k_ln_w + 4 * tid);
        float y[4] = {(k01.x - mu) * rs * wv.x, (k01.y - mu) * rs * wv.y,
                      (k23.x - mu) * rs * wv.z, (k23.y - mu) * rs * wv.w};
        float out[4];
        #pragma unroll
        for (int c = 0; c < 4; c++) {
            float p = __shfl_xor_sync(0xffffffffu, y[c], 8);
            out[c] = fmaf(sgn * p, sn[c], y[c] * cs[c]);
        }
        __half* dp = g_kh + obase;
        *(__half2*)(dp)     = __floats2half2_rn(out[0], out[1]);
        *(__half2*)(dp + 2) = __floats2half2_rn(out[2], out[3]);
    }
    // v copy (transpose only)
    {
        const __half* base = g_qkv_h + (size_t)t * (3 * D) + 2 * D + 4 * tid;
        *(uint2*)(g_vh + obase) = *(const uint2*)base;
    }
}

// Kernel 4: fp16 flash attention (R7/R9 design, unchanged)
constexpr int AST = 72;
constexpr int AKB = 64 * AST;
constexpr int ATTN_SMEM = (6 * AKB + 8 * 16 * AST) * 2;
constexpr int NKT = L / 64;

__global__ void __launch_bounds__(256) attn_f16(__half* __restrict__ ctx)
{
    extern __shared__ __half hsm[];
    const uint32_t ks0 = smem_u32(hsm);
    const uint32_t vs0 = smem_u32(hsm + 3 * AKB);
    __half* Qstage = hsm + 6 * AKB + (threadIdx.x >> 5) * 16 * AST;
    const uint32_t qs0 = smem_u32(Qstage);

    const int tid  = threadIdx.x;
    const int lane = tid & 31;
    const int g    = lane >> 2;
    const int tg   = lane & 3;
    const int w    = tid >> 5;
    const int bh   = blockIdx.y;
    const int bb   = bh / H;
    const int hh   = bh % H;
    const int q0   = blockIdx.x * 128;

    const __half* Kg0 = g_kh + (size_t)bh * L * DH;
    const __half* Vg0 = g_vh + (size_t)bh * L * DH;

    auto stage_kv = [&](int slot, int kt) {
        const __half* Kg = Kg0 + (size_t)kt * 64 * DH;
        const __half* Vg = Vg0 + (size_t)kt * 64 * DH;
        const uint32_t kd = ks0 + slot * AKB * 2;
        const uint32_t vd = vs0 + slot * AKB * 2;
        #pragma unroll
        for (int r = 0; r < 2; r++) {
            int idx = tid + r * 256;
            int row = idx >> 3, col = (idx & 7) * 8;
            cp_async16(kd + (row * AST + col) * 2, Kg + row * DH + col);
            cp_async16(vd + (row * AST + col) * 2, Vg + row * DH + col);
        }
    };

    stage_kv(0, 0); CP_COMMIT();
    stage_kv(1, 1); CP_COMMIT();

    uint32_t qa[4][4];
    {
        const __half* Qg = g_qh + ((size_t)bh * L + q0 + w * 16) * DH;
        #pragma unroll
        for (int r = 0; r < 4; r++) {
            int idx = lane + r * 32;
            int row = idx >> 3, col = (idx & 7) * 8;
            *(float4*)&Qstage[row * AST + col] = *(const float4*)(Qg + row * DH + col);
        }
        __syncwarp();
        const uint32_t qaddr = qs0 + ((lane & 15) * AST + (lane >> 4) * 8) * 2;
        #pragma unroll
        for (int ks = 0; ks < 4; ks++)
            LDMX4(qa[ks][0], qa[ks][1], qa[ks][2], qa[ks][3], qaddr + ks * 32);
    }

    float m0 = -1e30f, m1 = -1e30f, l0 = 0.0f, l1 = 0.0f;
    float o[8][4];
    #pragma unroll
    for (int nt = 0; nt < 8; nt++)
        #pragma unroll
        for (int i = 0; i < 4; i++) o[nt][i] = 0.0f;

    const uint32_t k_lane = (((lane & 7) + ((lane >> 4) << 3)) * AST +
                             ((lane >> 3) & 1) * 8) * 2;
    const uint32_t v_lane = (((lane & 7) + (((lane >> 3) & 1) << 3)) * AST +
                             ((lane >> 4) << 3)) * 2;

    for (int kt = 0; kt < NKT; kt++) {
        CP_WAIT1();
        __syncthreads();
        if (kt + 2 < NKT) stage_kv((kt + 2) % 3, kt + 2);
        CP_COMMIT();

        const uint32_t ksb = ks0 + (kt % 3) * AKB * 2;
        const uint32_t vsb = vs0 + (kt % 3) * AKB * 2;

        float s[8][4];
        #pragma unroll
        for (int nt = 0; nt < 8; nt++)
            #pragma unroll
            for (int i = 0; i < 4; i++) s[nt][i] = 0.0f;

        #pragma unroll
        for (int ks = 0; ks < 4; ks++) {
            uint32_t bk[8][2];
            #pragma unroll
            for (int p = 0; p < 4; p++)
                LDMX4(bk[2*p][0], bk[2*p][1], bk[2*p+1][0], bk[2*p+1][1],
                      ksb + p * 16 * AST * 2 + ks * 32 + k_lane);
            #pragma unroll
            for (int nt = 0; nt < 8; nt++) mma16(s[nt], qa[ks], bk[nt]);
        }

        float mx0 = -1e30f, mx1 = -1e30f;
        #pragma unroll
        for (int nt = 0; nt < 8; nt++) {
            mx0 = fmaxf(mx0, fmaxf(s[nt][0], s[nt][1]));
            mx1 = fmaxf(mx1, fmaxf(s[nt][2], s[nt][3]));
        }
        mx0 = fmaxf(mx0, __shfl_xor_sync(0xffffffffu, mx0, 1));
        mx0 = fmaxf(mx0, __shfl_xor_sync(0xffffffffu, mx0, 2));
        mx1 = fmaxf(mx1, __shfl_xor_sync(0xffffffffu, mx1, 1));
        mx1 = fmaxf(mx1, __shfl_xor_sync(0xffffffffu, mx1, 2));
        const float nm0 = fmaxf(m0, mx0);
        const float nm1 = fmaxf(m1, mx1);

        float sum0 = 0.0f, sum1 = 0.0f;
        uint32_t ph[8][2];
        #pragma unroll
        for (int nt = 0; nt < 8; nt++) {
            ph[nt][0] = packh2(__expf(s[nt][0] - nm0), __expf(s[nt][1] - nm0));
            ph[nt][1] = packh2(__expf(s[nt][2] - nm1), __expf(s[nt][3] - nm1));
            float2 f01 = __half22float2(*(__half2*)&ph[nt][0]);
            float2 f23 = __half22float2(*(__half2*)&ph[nt][1]);
            sum0 += f01.x + f01.y;
            sum1 += f23.x + f23.y;
        }
        sum0 += __shfl_xor_sync(0xffffffffu, sum0, 1);
        sum0 += __shfl_xor_sync(0xffffffffu, sum0, 2);
        sum1 += __shfl_xor_sync(0xffffffffu, sum1, 1);
        sum1 += __shfl_xor_sync(0xffffffffu, sum1, 2);

        const float al0 = __expf(m0 - nm0);
        const float al1 = __expf(m1 - nm1);
        l0 = l0 * al0 + sum0;  m0 = nm0;
        l1 = l1 * al1 + sum1;  m1 = nm1;

        #pragma unroll
        for (int nt = 0; nt < 8; nt++) {
            o[nt][0] *= al0; o[nt][1] *= al0;
            o[nt][2] *= al1; o[nt][3] *= al1;
        }

        #pragma unroll
        for (int ks = 0; ks < 4; ks++) {
            uint32_t a[4] = {ph[2*ks][0], ph[2*ks][1], ph[2*ks+1][0], ph[2*ks+1][1]};
            #pragma unroll
            for (int p = 0; p < 4; p++) {
                uint32_t b0, b1, b2, b3;
                LDMX4T(b0, b1, b2, b3, vsb + (ks * 16) * AST * 2 + p * 32 + v_lane);
                uint32_t bA[2] = {b0, b1}, bB[2] = {b2, b3};
                mma16(o[2*p],     a, bA);
                mma16(o[2*p + 1], a, bB);
            }
        }
    }

    const float inv0 = 1.0f / l0;
    const float inv1 = 1.0f / l1;
    const int row0 = q0 + w * 16 + g;
    const int row1 = row0 + 8;
    #pragma unroll
    for (int nt = 0; nt < 8; nt++) {
        const int col = hh * DH + nt * 8 + 2 * tg;
        *(__half2*)(ctx + (size_t)(bb * L + row0) * D + col) =
            __floats2half2_rn(o[nt][0] * inv0, o[nt][1] * inv0);
        *(__half2*)(ctx + (size_t)(bb * L + row1) * D + col) =
            __floats2half2_rn(o[nt][2] * inv1, o[nt][3] * inv1);
    }
}

// Launch
extern "C" void kernel_launch(void* const* d_in, const int* in_sizes, int n_in,
                              void* d_out, int out_size)
{
    const float* x      = (const float*)d_in[0];
    const float* ln_w   = (const float*)d_in[1];
    const float* ln_b   = (const float*)d_in[2];
    const float* w_qkv  = (const float*)d_in[3];
    const float* q_ln_w = (const float*)d_in[4];
    const float* k_ln_w = (const float*)d_in[5];
    const float* w_out  = (const float*)d_in[6];
    float* out = (float*)d_out;

    __half *hh, *wq, *wo, *qkv, *ctx;
    cudaGetSymbolAddress((void**)&hh,  g_h_h);
    cudaGetSymbolAddress((void**)&wq,  g_wqkv_h);
    cudaGetSymbolAddress((void**)&wo,  g_wout_h);
    cudaGetSymbolAddress((void**)&qkv, g_qkv_h);
    cudaGetSymbolAddress((void**)&ctx, g_ctx_h);

    cudaFuncSetAttribute(gemm_nt_f16<__half>, cudaFuncAttributeMaxDynamicSharedMemorySize, GEMM_SMEM);
    cudaFuncSetAttribute(gemm_nt_f16<float>,  cudaFuncAttributeMaxDynamicSharedMemorySize, GEMM_SMEM);
    cudaFuncSetAttribute(attn_f16, cudaFuncAttributeMaxDynamicSharedMemorySize, ATTN_SMEM);

    // LN + weight conversion + rope table in one launch
    ln_prep_kernel<<<BL + 4096 + 256, 256>>>(x, ln_w, ln_b, w_qkv, w_out);
    {
        dim3 grid(3 * D / 128, BL / 128);
        gemm_nt_f16<__half><<<grid, 256, GEMM_SMEM>>>(hh, wq, qkv, BL, 3 * D, D);
    }
    qk_rope_kernel<<<BL, 256>>>(q_ln_w, k_ln_w);
    {
        dim3 grid(L / 128, B * H);
        attn_f16<<<grid, 256, ATTN_SMEM>>>(ctx);
    }
    {
        dim3 grid(D / 128, BL / 128);
        gemm_nt_f16<float><<<grid, 256, GEMM_SMEM>>>(ctx, wo, out, BL, D, D);
    }
}

// round 11
// speedup vs baseline: 2.3773x; 1.0729x over previous
#include <cuda_runtime.h>
#include <cuda_fp16.h>
#include <math.h>
#include <stdint.h>

constexpr int B  = 2;
constexpr int L  = 2048;
constexpr int D  = 1024;
constexpr int H  = 16;
constexpr int DH = 64;
constexpr int BL = B * L;
constexpr float EPS = 1e-5f;
constexpr float LOG_ROPE_BASE = 9.210340371976184f;
constexpr float LOG2E = 1.4426950408889634f;

// Scratch
__device__ __half g_h_h[BL * D];
__device__ __half g_wqkv_h[3 * D * D];
__device__ __half g_wout_h[D * D];
__device__ __half g_qkv_h[BL * 3 * D];
__device__ __half g_qh[BL * D];     // pre-scaled by (1/8)*log2(e)
__device__ __half g_kh[BL * D];
__device__ __half g_vh[BL * D];
__device__ __half g_ctx_h[BL * D];
__device__ float2 g_rope[L * 32];

// Helpers
__device__ __forceinline__ uint32_t smem_u32(const void* p) {
    return (uint32_t)__cvta_generic_to_shared(p);
}
__device__ __forceinline__ void cp_async16(uint32_t dst, const void* src) {
    asm volatile("cp.async.cg.shared.global [%0], [%1], 16;" :: "r"(dst), "l"(src));
}
#define CP_COMMIT() asm volatile("cp.async.commit_group;")
#define CP_WAIT1()  asm volatile("cp.async.wait_group 1;")
#define LDMX4(r0,r1,r2,r3,addr) \
    asm volatile("ldmatrix.sync.aligned.m8n8.x4.shared.b16 {%0,%1,%2,%3},[%4];" \
                 : "=r"(r0),"=r"(r1),"=r"(r2),"=r"(r3) : "r"(addr))
#define LDMX4T(r0,r1,r2,r3,addr) \
    asm volatile("ldmatrix.sync.aligned.m8n8.x4.trans.shared.b16 {%0,%1,%2,%3},[%4];" \
                 : "=r"(r0),"=r"(r1),"=r"(r2),"=r"(r3) : "r"(addr))

__device__ __forceinline__ void mma16(float* c, const uint32_t* a, const uint32_t* b) {
    asm volatile(
        "mma.sync.aligned.m16n8k16.row.col.f32.f16.f16.f32 "
        "{%0,%1,%2,%3},{%4,%5,%6,%7},{%8,%9},{%0,%1,%2,%3};"
        : "+f"(c[0]), "+f"(c[1]), "+f"(c[2]), "+f"(c[3])
        : "r"(a[0]), "r"(a[1]), "r"(a[2]), "r"(a[3]), "r"(b[0]), "r"(b[1]));
}

__device__ __forceinline__ uint32_t packh2(float a, float b) {
    __half2 h = __floats2half2_rn(a, b);
    return *(uint32_t*)&h;
}
__device__ __forceinline__ float ex2f(float x) {
    float r; asm("ex2.approx.ftz.f32 %0, %1;" : "=f"(r) : "f"(x)); return r;
}

__device__ __forceinline__ float block_reduce_sum_256(float v, float* sbuf) {
    int tid = threadIdx.x;
    #pragma unroll
    for (int o = 16; o > 0; o >>= 1) v += __shfl_xor_sync(0xffffffffu, v, o);
    if ((tid & 31) == 0) sbuf[tid >> 5] = v;
    __syncthreads();
    if (tid < 8) {
        float w = sbuf[tid];
        #pragma unroll
        for (int o = 4; o > 0; o >>= 1) w += __shfl_xor_sync(0xffu, w, o);
        if (tid == 0) sbuf[0] = w;
    }
    __syncthreads();
    float r = sbuf[0];
    __syncthreads();
    return r;
}

__device__ __forceinline__ float4 block_reduce_sum4(float4 v) {
    __shared__ float4 sb[8];
    const int tid = threadIdx.x;
    #pragma unroll
    for (int o = 16; o > 0; o >>= 1) {
        v.x += __shfl_xor_sync(0xffffffffu, v.x, o);
        v.y += __shfl_xor_sync(0xffffffffu, v.y, o);
        v.z += __shfl_xor_sync(0xffffffffu, v.z, o);
        v.w += __shfl_xor_sync(0xffffffffu, v.w, o);
    }
    if ((tid & 31) == 0) sb[tid >> 5] = v;
    __syncthreads();
    if (tid < 8) {
        float4 w = sb[tid];
        #pragma unroll
        for (int o = 4; o > 0; o >>= 1) {
            w.x += __shfl_xor_sync(0xffu, w.x, o);
            w.y += __shfl_xor_sync(0xffu, w.y, o);
            w.z += __shfl_xor_sync(0xffu, w.z, o);
            w.w += __shfl_xor_sync(0xffu, w.w, o);
        }
        if (tid == 0) sb[0] = w;
    }
    __syncthreads();
    return sb[0];
}

// ---------------------------------------------------------------------------
// Kernel 1 (merged): LN + weight fp16 conversion + rope table
// ---------------------------------------------------------------------------
__global__ void __launch_bounds__(256) ln_prep_kernel(
    const float* __restrict__ x, const float* __restrict__ w,
    const float* __restrict__ bias,
    const float* __restrict__ wq, const float* __restrict__ wo)
{
    const int bid = blockIdx.x;
    const int tid = threadIdx.x;
    if (bid < BL) {
        __shared__ float sbuf[8];
        const int t = bid;
        const float4 xv = *(const float4*)(x + (size_t)t * D + 4 * tid);
        float s  = xv.x + xv.y + xv.z + xv.w;
        float ss = fmaf(xv.x, xv.x, fmaf(xv.y, xv.y, fmaf(xv.z, xv.z, xv.w * xv.w)));
        s  = block_reduce_sum_256(s,  sbuf);
        ss = block_reduce_sum_256(ss, sbuf);
        const float mu = s * (1.0f / D);
        const float rs = rsqrtf(ss * (1.0f / D) - mu * mu + EPS);
        const float4 wv = *(const float4*)(w    + 4 * tid);
        const float4 bv = *(const float4*)(bias + 4 * tid);
        __half* dst = g_h_h + (size_t)t * D + 4 * tid;
        *(__half2*)(dst)     = __floats2half2_rn((xv.x - mu) * rs * wv.x + bv.x,
                                                 (xv.y - mu) * rs * wv.y + bv.y);
        *(__half2*)(dst + 2) = __floats2half2_rn((xv.z - mu) * rs * wv.z + bv.z,
                                                 (xv.w - mu) * rs * wv.w + bv.w);
    } else if (bid < BL + 4096) {
        const size_t i4 = ((size_t)(bid - BL) * 256 + tid) * 4;
        const size_t n1 = (size_t)3 * D * D;
        if (i4 < n1) {
            float4 v = *(const float4*)(wq + i4);
            *(__half2*)(g_wqkv_h + i4)     = __floats2half2_rn(v.x, v.y);
            *(__half2*)(g_wqkv_h + i4 + 2) = __floats2half2_rn(v.z, v.w);
        } else {
            size_t j = i4 - n1;
            float4 v = *(const float4*)(wo + j);
            *(__half2*)(g_wout_h + j)     = __floats2half2_rn(v.x, v.y);
            *(__half2*)(g_wout_h + j + 2) = __floats2half2_rn(v.z, v.w);
        }
    } else {
        const int idx = (bid - BL - 4096) * 256 + tid;
        const int l = idx >> 5;
        const int i = idx & 31;
        float inv_freq = expf(-(float)(2 * i) * (1.0f / 64.0f) * LOG_ROPE_BASE);
        float sn, cs;
        sincosf((float)l * inv_freq, &sn, &cs);
        g_rope[idx] = make_float2(cs, sn);
    }
}

// ---------------------------------------------------------------------------
// Kernel 2/5: fp16 GEMM-NT, K-chunk 64, 3-stage cp.async ring.
// ---------------------------------------------------------------------------
constexpr int GST  = 72;
constexpr int GBUF = 128 * GST * 2;
constexpr int GEMM_SMEM = 6 * GBUF;

__device__ __forceinline__ void store2(float* p, float a, float b) {
    *(float2*)p = make_float2(a, b);
}
__device__ __forceinline__ void store2(__half* p, float a, float b) {
    *(__half2*)p = __floats2half2_rn(a, b);
}

template <typename TOut>
__global__ void __launch_bounds__(256) gemm_nt_f16(
    const __half* __restrict__ A, const __half* __restrict__ Bm,
    TOut* __restrict__ C, int M, int N, int K)
{
    extern __shared__ __half gsm[];
    const uint32_t as0 = smem_u32(gsm);
    const uint32_t bs0 = smem_u32(gsm + 3 * 128 * GST);

    const int tid  = threadIdx.x;
    const int lane = tid & 31;
    const int g    = lane >> 2;
    const int tg   = lane & 3;
    const int wid  = tid >> 5;
    const int wm   = wid >> 2;
    const int wn   = wid & 3;
    const int m0   = blockIdx.y * 128;
    const int n0   = blockIdx.x * 128;

    float acc[4][4][4];
    #pragma unroll
    for (int mt = 0; mt < 4; mt++)
        #pragma unroll
        for (int nt = 0; nt < 4; nt++)
            #pragma unroll
            for (int i = 0; i < 4; i++) acc[mt][nt][i] = 0.0f;

    auto stage = [&](int s, int k0) {
        #pragma unroll
        for (int r = 0; r < 4; r++) {
            int qid = tid + r * 256;
            int row = qid >> 3;
            int cq  = (qid & 7) * 8;
            cp_async16(as0 + s * GBUF + (row * GST + cq) * 2,
                       A + (size_t)(m0 + row) * K + k0 + cq);
            cp_async16(bs0 + s * GBUF + (row * GST + cq) * 2,
                       Bm + (size_t)(n0 + row) * K + k0 + cq);
        }
    };
    stage(0, 0);  CP_COMMIT();
    stage(1, 64); CP_COMMIT();

    const uint32_t a_lane = ((lane & 15) * GST + (lane >> 4) * 8) * 2;
    const uint32_t b_lane = ((((lane >> 4) << 3) + (lane & 7)) * GST +
                             ((lane >> 3) & 1) * 8) * 2;

    const int NIT = K / 64;
    for (int kt = 0; kt < NIT; kt++) {
        CP_WAIT1();
        __syncthreads();
        if (kt + 2 < NIT) stage((kt + 2) % 3, (kt + 2) * 64);
        CP_COMMIT();

        const uint32_t ab = as0 + (kt % 3) * GBUF + (wm * 64) * GST * 2 + a_lane;
        const uint32_t bb = bs0 + (kt % 3) * GBUF + (wn * 32) * GST * 2 + b_lane;

        #pragma unroll
        for (int kk = 0; kk < 4; kk++) {
            uint32_t bf[4][2];
            #pragma unroll
            for (int p = 0; p < 2; p++)
                LDMX4(bf[2*p][0], bf[2*p][1], bf[2*p+1][0], bf[2*p+1][1],
                      bb + p * 16 * GST * 2 + kk * 32);
            #pragma unroll
            for (int mt = 0; mt < 4; mt++) {
                uint32_t a[4];
                LDMX4(a[0], a[1], a[2], a[3], ab + mt * 16 * GST * 2 + kk * 32);
                #pragma unroll
                for (int nt = 0; nt < 4; nt++) mma16(acc[mt][nt], a, bf[nt]);
            }
        }
    }

    #pragma unroll
    for (int mt = 0; mt < 4; mt++) {
        const int m = m0 + wm * 64 + mt * 16 + g;
        #pragma unroll
        for (int nt = 0; nt < 4; nt++) {
            const int n = n0 + wn * 32 + nt * 8 + 2 * tg;
            store2(C + (size_t)m * N + n,       acc[mt][nt][0], acc[mt][nt][1]);
            store2(C + (size_t)(m + 8) * N + n, acc[mt][nt][2], acc[mt][nt][3]);
        }
    }
}

// ---------------------------------------------------------------------------
// Kernel 3: q/k LN + RoPE (shfl rotation). Q scaled by (1/8)*log2(e).
// ---------------------------------------------------------------------------
__global__ void __launch_bounds__(256) qk_rope_kernel(
    const float* __restrict__ q_ln_w, const float* __restrict__ k_ln_w)
{
    const int t = blockIdx.x, tid = threadIdx.x;
    const int b = t / L, l = t % L;

    const int i0 = (4 * tid) & 31;
    float4 rc0 = *(const float4*)(g_rope + l * 32 + i0);
    float4 rc1 = *(const float4*)(g_rope + l * 32 + i0 + 2);
    const float cs[4] = {rc0.x, rc0.z, rc1.x, rc1.z};
    const float sn[4] = {rc0.y, rc0.w, rc1.y, rc1.w};
    const float sgn = (tid & 8) ? 1.0f : -1.0f;

    const __half* qb = g_qkv_h + (size_t)t * (3 * D) + 4 * tid;
    float2 q01 = __half22float2(*(const __half2*)(qb));
    float2 q23 = __half22float2(*(const __half2*)(qb + 2));
    float2 k01 = __half22float2(*(const __half2*)(qb + D));
    float2 k23 = __half22float2(*(const __half2*)(qb + D + 2));

    float4 r;
    r.x = q01.x + q01.y + q23.x + q23.y;
    r.y = fmaf(q01.x, q01.x, fmaf(q01.y, q01.y, fmaf(q23.x, q23.x, q23.y * q23.y)));
    r.z = k01.x + k01.y + k23.x + k23.y;
    r.w = fmaf(k01.x, k01.x, fmaf(k01.y, k01.y, fmaf(k23.x, k23.x, k23.y * k23.y)));
    r = block_reduce_sum4(r);

    const int d0 = 4 * tid, head = d0 >> 6, dh0 = d0 & 63;
    const size_t obase = ((size_t)(b * H + head) * L + l) * DH + dh0;

    // q segment (scaled into exp2 domain)
    {
        const float mu = r.x * (1.0f / D);
        const float rs = rsqrtf(r.y * (1.0f / D) - mu * mu + EPS);
        const float4 wv = *(const float4*)(q_ln_w + 4 * tid);
        float y[4] = {(q01.x - mu) * rs * wv.x, (q01.y - mu) * rs * wv.y,
                      (q23.x - mu) * rs * wv.z, (q23.y - mu) * rs * wv.w};
        float out[4];
        #pragma unroll
        for (int c = 0; c < 4; c++) {
            float p = __shfl_xor_sync(0xffffffffu, y[c], 8);
            out[c] = fmaf(sgn * p, sn[c], y[c] * cs[c]);
        }
        const float QS = 0.125f * LOG2E;
        __half* dp = g_qh + obase;
        *(__half2*)(dp)     = __floats2half2_rn(out[0] * QS, out[1] * QS);
        *(__half2*)(dp + 2) = __floats2half2_rn(out[2] * QS, out[3] * QS);
    }
    // k segment
    {
        const float mu = r.z * (1.0f / D);
        const float rs = rsqrtf(r.w * (1.0f / D) - mu * mu + EPS);
        const float4 wv = *(const float4*)(k_ln_w + 4 * tid);
        float y[4] = {(k01.x - mu) * rs * wv.x, (k01.y - mu) * rs * wv.y,
                      (k23.x - mu) * rs * wv.z, (k23.y - mu) * rs * wv.w};
        float out[4];
        #pragma unroll
        for (int c = 0; c < 4; c++) {
            float p = __shfl_xor_sync(0xffffffffu, y[c], 8);
            out[c] = fmaf(sgn * p, sn[c], y[c] * cs[c]);
        }
        __half* dp = g_kh + obase;
        *(__half2*)(dp)     = __floats2half2_rn(out[0], out[1]);
        *(__half2*)(dp + 2) = __floats2half2_rn(out[2], out[3]);
    }
    // v copy
    {
        const __half* base = g_qkv_h + (size_t)t * (3 * D) + 2 * D + 4 * tid;
        *(uint2*)(g_vh + obase) = *(const uint2*)base;
    }
}

// ---------------------------------------------------------------------------
// Kernel 4: fp16 flash attention; S in exp2 domain, lean softmax stream.
// ---------------------------------------------------------------------------
constexpr int AST = 72;
constexpr int AKB = 64 * AST;
constexpr int ATTN_SMEM = (6 * AKB + 8 * 16 * AST) * 2;
constexpr int NKT = L / 64;

__global__ void __launch_bounds__(256) attn_f16(__half* __restrict__ ctx)
{
    extern __shared__ __half hsm[];
    const uint32_t ks0 = smem_u32(hsm);
    const uint32_t vs0 = smem_u32(hsm + 3 * AKB);
    __half* Qstage = hsm + 6 * AKB + (threadIdx.x >> 5) * 16 * AST;
    const uint32_t qs0 = smem_u32(Qstage);

    const int tid  = threadIdx.x;
    const int lane = tid & 31;
    const int g    = lane >> 2;
    const int tg   = lane & 3;
    const int w    = tid >> 5;
    const int bh   = blockIdx.y;
    const int bb   = bh / H;
    const int hh   = bh % H;
    const int q0   = blockIdx.x * 128;

    const __half* Kg0 = g_kh + (size_t)bh * L * DH;
    const __half* Vg0 = g_vh + (size_t)bh * L * DH;

    auto stage_kv = [&](int slot, int kt) {
        const __half* Kg = Kg0 + (size_t)kt * 64 * DH;
        const __half* Vg = Vg0 + (size_t)kt * 64 * DH;
        const uint32_t kd = ks0 + slot * AKB * 2;
        const uint32_t vd = vs0 + slot * AKB * 2;
        #pragma unroll
        for (int r = 0; r < 2; r++) {
            int idx = tid + r * 256;
            int row = idx >> 3, col = (idx & 7) * 8;
            cp_async16(kd + (row * AST + col) * 2, Kg + row * DH + col);
            cp_async16(vd + (row * AST + col) * 2, Vg + row * DH + col);
        }
    };

    stage_kv(0, 0); CP_COMMIT();
    stage_kv(1, 1); CP_COMMIT();

    uint32_t qa[4][4];
    {
        const __half* Qg = g_qh + ((size_t)bh * L + q0 + w * 16) * DH;
        #pragma unroll
        for (int r = 0; r < 4; r++) {
            int idx = lane + r * 32;
            int row = idx >> 3, col = (idx & 7) * 8;
            *(float4*)&Qstage[row * AST + col] = *(const float4*)(Qg + row * DH + col);
        }
        __syncwarp();
        const uint32_t qaddr = qs0 + ((lane & 15) * AST + (lane >> 4) * 8) * 2;
        #pragma unroll
        for (int ks = 0; ks < 4; ks++)
            LDMX4(qa[ks][0], qa[ks][1], qa[ks][2], qa[ks][3], qaddr + ks * 32);
    }

    float m0 = -1e30f, m1 = -1e30f, l0 = 0.0f, l1 = 0.0f;
    float o[8][4];
    #pragma unroll
    for (int nt = 0; nt < 8; nt++)
        #pragma unroll
        for (int i = 0; i < 4; i++) o[nt][i] = 0.0f;

    const uint32_t k_lane = (((lane & 7) + ((lane >> 4) << 3)) * AST +
                             ((lane >> 3) & 1) * 8) * 2;
    const uint32_t v_lane = (((lane & 7) + (((lane >> 3) & 1) << 3)) * AST +
                             ((lane >> 4) << 3)) * 2;

    for (int kt = 0; kt < NKT; kt++) {
        CP_WAIT1();
        __syncthreads();
        if (kt + 2 < NKT) stage_kv((kt + 2) % 3, kt + 2);
        CP_COMMIT();

        const uint32_t ksb = ks0 + (kt % 3) * AKB * 2;
        const uint32_t vsb = vs0 + (kt % 3) * AKB * 2;

        // S = Q' K^T (S already in exp2 domain)
        float s[8][4];
        #pragma unroll
        for (int nt = 0; nt < 8; nt++)
            #pragma unroll
            for (int i = 0; i < 4; i++) s[nt][i] = 0.0f;

        #pragma unroll
        for (int ks = 0; ks < 4; ks++) {
            uint32_t bk[8][2];
            #pragma unroll
            for (int p = 0; p < 4; p++)
                LDMX4(bk[2*p][0], bk[2*p][1], bk[2*p+1][0], bk[2*p+1][1],
                      ksb + p * 16 * AST * 2 + ks * 32 + k_lane);
            #pragma unroll
            for (int nt = 0; nt < 8; nt++) mma16(s[nt], qa[ks], bk[nt]);
        }

        // online softmax (exp2 domain)
        float mx0 = -1e30f, mx1 = -1e30f;
        #pragma unroll
        for (int nt = 0; nt < 8; nt++) {
            mx0 = fmaxf(mx0, fmaxf(s[nt][0], s[nt][1]));
            mx1 = fmaxf(mx1, fmaxf(s[nt][2], s[nt][3]));
        }
        mx0 = fmaxf(mx0, __shfl_xor_sync(0xffffffffu, mx0, 1));
        mx0 = fmaxf(mx0, __shfl_xor_sync(0xffffffffu, mx0, 2));
        mx1 = fmaxf(mx1, __shfl_xor_sync(0xffffffffu, mx1, 1));
        mx1 = fmaxf(mx1, __shfl_xor_sync(0xffffffffu, mx1, 2));
        const float nm0 = fmaxf(m0, mx0);
        const float nm1 = fmaxf(m1, mx1);

        float sum0 = 0.0f, sum1 = 0.0f;
        uint32_t ph[8][2];
        #pragma unroll
        for (int nt = 0; nt < 8; nt++) {
            float e0 = ex2f(s[nt][0] - nm0);
            float e1 = ex2f(s[nt][1] - nm0);
            float e2 = ex2f(s[nt][2] - nm1);
            float e3 = ex2f(s[nt][3] - nm1);
            sum0 += e0 + e1;
            sum1 += e2 + e3;
            ph[nt][0] = packh2(e0, e1);
            ph[nt][1] = packh2(e2, e3);
        }
        sum0 += __shfl_xor_sync(0xffffffffu, sum0, 1);
        sum0 += __shfl_xor_sync(0xffffffffu, sum0, 2);
        sum1 += __shfl_xor_sync(0xffffffffu, sum1, 1);
        sum1 += __shfl_xor_sync(0xffffffffu, sum1, 2);

        const float al0 = ex2f(m0 - nm0);
        const float al1 = ex2f(m1 - nm1);
        l0 = l0 * al0 + sum0;  m0 = nm0;
        l1 = l1 * al1 + sum1;  m1 = nm1;

        #pragma unroll
        for (int nt = 0; nt < 8; nt++) {
            o[nt][0] *= al0; o[nt][1] *= al0;
            o[nt][2] *= al1; o[nt][3] *= al1;
        }

        #pragma unroll
        for (int ks = 0; ks < 4; ks++) {
            uint32_t a[4] = {ph[2*ks][0], ph[2*ks][1], ph[2*ks+1][0], ph[2*ks+1][1]};
            #pragma unroll
            for (int p = 0; p < 4; p++) {
                uint32_t b0, b1, b2, b3;
                LDMX4T(b0, b1, b2, b3, vsb + (ks * 16) * AST * 2 + p * 32 + v_lane);
                uint32_t bA[2] = {b0, b1}, bB[2] = {b2, b3};
                mma16(o[2*p],     a, bA);
                mma16(o[2*p + 1], a, bB);
            }
        }
    }

    const float inv0 = 1.0f / l0;
    const float inv1 = 1.0f / l1;
    const int row0 = q0 + w * 16 + g;
    const int row1 = row0 + 8;
    #pragma unroll
    for (int nt = 0; nt < 8; nt++) {
        const int col = hh * DH + nt * 8 + 2 * tg;
        *(__half2*)(ctx + (size_t)(bb * L + row0) * D + col) =
            __floats2half2_rn(o[nt][0] * inv0, o[nt][1] * inv0);
        *(__half2*)(ctx + (size_t)(bb * L + row1) * D + col) =
            __floats2half2_rn(o[nt][2] * inv1, o[nt][3] * inv1);
    }
}

// Launch
extern "C" void kernel_launch(void* const* d_in, const int* in_sizes, int n_in,
                              void* d_out, int out_size)
{
    const float* x      = (const float*)d_in[0];
    const float* ln_w   = (const float*)d_in[1];
    const float* ln_b   = (const float*)d_in[2];
    const float* w_qkv  = (const float*)d_in[3];
    const float* q_ln_w = (const float*)d_in[4];
    const float* k_ln_w = (const float*)d_in[5];
    const float* w_out  = (const float*)d_in[6];
    float* out = (float*)d_out;

    __half *hh, *wq, *wo, *qkv, *ctx;
    cudaGetSymbolAddress((void**)&hh,  g_h_h);
    cudaGetSymbolAddress((void**)&wq,  g_wqkv_h);
    cudaGetSymbolAddress((void**)&wo,  g_wout_h);
    cudaGetSymbolAddress((void**)&qkv, g_qkv_h);
    cudaGetSymbolAddress((void**)&ctx, g_ctx_h);

    cudaFuncSetAttribute(gemm_nt_f16<__half>, cudaFuncAttributeMaxDynamicSharedMemorySize, GEMM_SMEM);
    cudaFuncSetAttribute(gemm_nt_f16<float>,  cudaFuncAttributeMaxDynamicSharedMemorySize, GEMM_SMEM);
    cudaFuncSetAttribute(attn_f16, cudaFuncAttributeMaxDynamicSharedMemorySize, ATTN_SMEM);

    ln_prep_kernel<<<BL + 4096 + 256, 256>>>(x, ln_w, ln_b, w_qkv, w_out);
    {
        dim3 grid(3 * D / 128, BL / 128);
        gemm_nt_f16<__half><<<grid, 256, GEMM_SMEM>>>(hh, wq, qkv, BL, 3 * D, D);
    }
    qk_rope_kernel<<<BL, 256>>>(q_ln_w, k_ln_w);
    {
        dim3 grid(L / 128, B * H);
        attn_f16<<<grid, 256, ATTN_SMEM>>>(ctx);
    }
    {
        dim3 grid(D / 128, BL / 128);
        gemm_nt_f16<float><<<grid, 256, GEMM_SMEM>>>(ctx, wo, out, BL, D, D);
    }
}

// round 12
// speedup vs baseline: 2.4027x; 1.0107x over previous
#include <cuda_runtime.h>
#include <cuda_fp16.h>
#include <math.h>
#include <stdint.h>

constexpr int B  = 2;
constexpr int L  = 2048;
constexpr int D  = 1024;
constexpr int H  = 16;
constexpr int DH = 64;
constexpr int BL = B * L;
constexpr float EPS = 1e-5f;
constexpr float LOG_ROPE_BASE = 9.210340371976184f;
constexpr float LOG2E = 1.4426950408889634f;

// Scratch
__device__ __half g_h_h[BL * D];
__device__ __half g_wqkv_h[3 * D * D];
__device__ __half g_wout_h[D * D];
__device__ __half g_qkv_h[BL * 3 * D];
__device__ __half g_qh[BL * D];     // pre-scaled by (1/8)*log2(e)
__device__ __half g_kh[BL * D];
__device__ __half g_vh[BL * D];
__device__ __half g_ctx_h[BL * D];
__device__ float2 g_rope[L * 32];

// Helpers
__device__ __forceinline__ uint32_t smem_u32(const void* p) {
    return (uint32_t)__cvta_generic_to_shared(p);
}
__device__ __forceinline__ void cp_async16(uint32_t dst, const void* src) {
    asm volatile("cp.async.cg.shared.global [%0], [%1], 16;" :: "r"(dst), "l"(src));
}
#define CP_COMMIT() asm volatile("cp.async.commit_group;")
#define CP_WAIT1()  asm volatile("cp.async.wait_group 1;")
#define CP_WAIT2()  asm volatile("cp.async.wait_group 2;")
#define LDMX4(r0,r1,r2,r3,addr) \
    asm volatile("ldmatrix.sync.aligned.m8n8.x4.shared.b16 {%0,%1,%2,%3},[%4];" \
                 : "=r"(r0),"=r"(r1),"=r"(r2),"=r"(r3) : "r"(addr))
#define LDMX4T(r0,r1,r2,r3,addr) \
    asm volatile("ldmatrix.sync.aligned.m8n8.x4.trans.shared.b16 {%0,%1,%2,%3},[%4];" \
                 : "=r"(r0),"=r"(r1),"=r"(r2),"=r"(r3) : "r"(addr))

__device__ __forceinline__ void mma16(float* c, const uint32_t* a, const uint32_t* b) {
    asm volatile(
        "mma.sync.aligned.m16n8k16.row.col.f32.f16.f16.f32 "
        "{%0,%1,%2,%3},{%4,%5,%6,%7},{%8,%9},{%0,%1,%2,%3};"
        : "+f"(c[0]), "+f"(c[1]), "+f"(c[2]), "+f"(c[3])
        : "r"(a[0]), "r"(a[1]), "r"(a[2]), "r"(a[3]), "r"(b[0]), "r"(b[1]));
}

__device__ __forceinline__ uint32_t packh2(float a, float b) {
    __half2 h = __floats2half2_rn(a, b);
    return *(uint32_t*)&h;
}
__device__ __forceinline__ float ex2f(float x) {
    float r; asm("ex2.approx.ftz.f32 %0, %1;" : "=f"(r) : "f"(x)); return r;
}

// Fused 2-value block reduction (one barrier pair)
__device__ __forceinline__ float2 block_reduce_sum2(float2 v) {
    __shared__ float2 sb2[8];
    const int tid = threadIdx.x;
    #pragma unroll
    for (int o = 16; o > 0; o >>= 1) {
        v.x += __shfl_xor_sync(0xffffffffu, v.x, o);
        v.y += __shfl_xor_sync(0xffffffffu, v.y, o);
    }
    if ((tid & 31) == 0) sb2[tid >> 5] = v;
    __syncthreads();
    if (tid < 8) {
        float2 w = sb2[tid];
        #pragma unroll
        for (int o = 4; o > 0; o >>= 1) {
            w.x += __shfl_xor_sync(0xffu, w.x, o);
            w.y += __shfl_xor_sync(0xffu, w.y, o);
        }
        if (tid == 0) sb2[0] = w;
    }
    __syncthreads();
    return sb2[0];
}

__device__ __forceinline__ float4 block_reduce_sum4(float4 v) {
    __shared__ float4 sb[8];
    const int tid = threadIdx.x;
    #pragma unroll
    for (int o = 16; o > 0; o >>= 1) {
        v.x += __shfl_xor_sync(0xffffffffu, v.x, o);
        v.y += __shfl_xor_sync(0xffffffffu, v.y, o);
        v.z += __shfl_xor_sync(0xffffffffu, v.z, o);
        v.w += __shfl_xor_sync(0xffffffffu, v.w, o);
    }
    if ((tid & 31) == 0) sb[tid >> 5] = v;
    __syncthreads();
    if (tid < 8) {
        float4 w = sb[tid];
        #pragma unroll
        for (int o = 4; o > 0; o >>= 1) {
            w.x += __shfl_xor_sync(0xffu, w.x, o);
            w.y += __shfl_xor_sync(0xffu, w.y, o);
            w.z += __shfl_xor_sync(0xffu, w.z, o);
            w.w += __shfl_xor_sync(0xffu, w.w, o);
        }
        if (tid == 0) sb[0] = w;
    }
    __syncthreads();
    return sb[0];
}

// ---------------------------------------------------------------------------
// Kernel 1 (merged): LN + weight fp16 conversion + rope table
// ---------------------------------------------------------------------------
__global__ void __launch_bounds__(256) ln_prep_kernel(
    const float* __restrict__ x, const float* __restrict__ w,
    const float* __restrict__ bias,
    const float* __restrict__ wq, const float* __restrict__ wo)
{
    const int bid = blockIdx.x;
    const int tid = threadIdx.x;
    if (bid < BL) {
        const int t = bid;
        const float4 xv = *(const float4*)(x + (size_t)t * D + 4 * tid);
        float2 r;
        r.x = xv.x + xv.y + xv.z + xv.w;
        r.y = fmaf(xv.x, xv.x, fmaf(xv.y, xv.y, fmaf(xv.z, xv.z, xv.w * xv.w)));
        r = block_reduce_sum2(r);
        const float mu = r.x * (1.0f / D);
        const float rs = rsqrtf(r.y * (1.0f / D) - mu * mu + EPS);
        const float4 wv = *(const float4*)(w    + 4 * tid);
        const float4 bv = *(const float4*)(bias + 4 * tid);
        __half* dst = g_h_h + (size_t)t * D + 4 * tid;
        *(__half2*)(dst)     = __floats2half2_rn((xv.x - mu) * rs * wv.x + bv.x,
                                                 (xv.y - mu) * rs * wv.y + bv.y);
        *(__half2*)(dst + 2) = __floats2half2_rn((xv.z - mu) * rs * wv.z + bv.z,
                                                 (xv.w - mu) * rs * wv.w + bv.w);
    } else if (bid < BL + 4096) {
        const size_t i4 = ((size_t)(bid - BL) * 256 + tid) * 4;
        const size_t n1 = (size_t)3 * D * D;
        if (i4 < n1) {
            float4 v = *(const float4*)(wq + i4);
            *(__half2*)(g_wqkv_h + i4)     = __floats2half2_rn(v.x, v.y);
            *(__half2*)(g_wqkv_h + i4 + 2) = __floats2half2_rn(v.z, v.w);
        } else {
            size_t j = i4 - n1;
            float4 v = *(const float4*)(wo + j);
            *(__half2*)(g_wout_h + j)     = __floats2half2_rn(v.x, v.y);
            *(__half2*)(g_wout_h + j + 2) = __floats2half2_rn(v.z, v.w);
        }
    } else {
        const int idx = (bid - BL - 4096) * 256 + tid;
        const int l = idx >> 5;
        const int i = idx & 31;
        float inv_freq = expf(-(float)(2 * i) * (1.0f / 64.0f) * LOG_ROPE_BASE);
        float sn, cs;
        sincosf((float)l * inv_freq, &sn, &cs);
        g_rope[idx] = make_float2(cs, sn);
    }
}

// ---------------------------------------------------------------------------
// Kernel 2/5: fp16 GEMM-NT, K-chunk 64, 3-stage cp.async ring.
// ---------------------------------------------------------------------------
constexpr int GST  = 72;
constexpr int GBUF = 128 * GST * 2;
constexpr int GEMM_SMEM = 6 * GBUF;

__device__ __forceinline__ void store2(float* p, float a, float b) {
    *(float2*)p = make_float2(a, b);
}
__device__ __forceinline__ void store2(__half* p, float a, float b) {
    *(__half2*)p = __floats2half2_rn(a, b);
}

template <typename TOut>
__global__ void __launch_bounds__(256) gemm_nt_f16(
    const __half* __restrict__ A, const __half* __restrict__ Bm,
    TOut* __restrict__ C, int M, int N, int K)
{
    extern __shared__ __half gsm[];
    const uint32_t as0 = smem_u32(gsm);
    const uint32_t bs0 = smem_u32(gsm + 3 * 128 * GST);

    const int tid  = threadIdx.x;
    const int lane = tid & 31;
    const int g    = lane >> 2;
    const int tg   = lane & 3;
    const int wid  = tid >> 5;
    const int wm   = wid >> 2;
    const int wn   = wid & 3;
    const int m0   = blockIdx.y * 128;
    const int n0   = blockIdx.x * 128;

    float acc[4][4][4];
    #pragma unroll
    for (int mt = 0; mt < 4; mt++)
        #pragma unroll
        for (int nt = 0; nt < 4; nt++)
            #pragma unroll
            for (int i = 0; i < 4; i++) acc[mt][nt][i] = 0.0f;

    auto stage = [&](int s, int k0) {
        #pragma unroll
        for (int r = 0; r < 4; r++) {
            int qid = tid + r * 256;
            int row = qid >> 3;
            int cq  = (qid & 7) * 8;
            cp_async16(as0 + s * GBUF + (row * GST + cq) * 2,
                       A + (size_t)(m0 + row) * K + k0 + cq);
            cp_async16(bs0 + s * GBUF + (row * GST + cq) * 2,
                       Bm + (size_t)(n0 + row) * K + k0 + cq);
        }
    };
    stage(0, 0);  CP_COMMIT();
    stage(1, 64); CP_COMMIT();

    const uint32_t a_lane = ((lane & 15) * GST + (lane >> 4) * 8) * 2;
    const uint32_t b_lane = ((((lane >> 4) << 3) + (lane & 7)) * GST +
                             ((lane >> 3) & 1) * 8) * 2;

    const int NIT = K / 64;
    for (int kt = 0; kt < NIT; kt++) {
        CP_WAIT1();
        __syncthreads();
        if (kt + 2 < NIT) stage((kt + 2) % 3, (kt + 2) * 64);
        CP_COMMIT();

        const uint32_t ab = as0 + (kt % 3) * GBUF + (wm * 64) * GST * 2 + a_lane;
        const uint32_t bb = bs0 + (kt % 3) * GBUF + (wn * 32) * GST * 2 + b_lane;

        #pragma unroll
        for (int kk = 0; kk < 4; kk++) {
            uint32_t bf[4][2];
            #pragma unroll
            for (int p = 0; p < 2; p++)
                LDMX4(bf[2*p][0], bf[2*p][1], bf[2*p+1][0], bf[2*p+1][1],
                      bb + p * 16 * GST * 2 + kk * 32);
            #pragma unroll
            for (int mt = 0; mt < 4; mt++) {
                uint32_t a[4];
                LDMX4(a[0], a[1], a[2], a[3], ab + mt * 16 * GST * 2 + kk * 32);
                #pragma unroll
                for (int nt = 0; nt < 4; nt++) mma16(acc[mt][nt], a, bf[nt]);
            }
        }
    }

    #pragma unroll
    for (int mt = 0; mt < 4; mt++) {
        const int m = m0 + wm * 64 + mt * 16 + g;
        #pragma unroll
        for (int nt = 0; nt < 4; nt++) {
            const int n = n0 + wn * 32 + nt * 8 + 2 * tg;
            store2(C + (size_t)m * N + n,       acc[mt][nt][0], acc[mt][nt][1]);
            store2(C + (size_t)(m + 8) * N + n, acc[mt][nt][2], acc[mt][nt][3]);
        }
    }
}

// ---------------------------------------------------------------------------
// Kernel 3: q/k LN + RoPE (shfl rotation). Q scaled by (1/8)*log2(e).
// ---------------------------------------------------------------------------
__global__ void __launch_bounds__(256) qk_rope_kernel(
    const float* __restrict__ q_ln_w, const float* __restrict__ k_ln_w)
{
    const int t = blockIdx.x, tid = threadIdx.x;
    const int b = t / L, l = t % L;

    const int i0 = (4 * tid) & 31;
    float4 rc0 = *(const float4*)(g_rope + l * 32 + i0);
    float4 rc1 = *(const float4*)(g_rope + l * 32 + i0 + 2);
    const float cs[4] = {rc0.x, rc0.z, rc1.x, rc1.z};
    const float sn[4] = {rc0.y, rc0.w, rc1.y, rc1.w};
    const float sgn = (tid & 8) ? 1.0f : -1.0f;

    const __half* qb = g_qkv_h + (size_t)t * (3 * D) + 4 * tid;
    float2 q01 = __half22float2(*(const __half2*)(qb));
    float2 q23 = __half22float2(*(const __half2*)(qb + 2));
    float2 k01 = __half22float2(*(const __half2*)(qb + D));
    float2 k23 = __half22float2(*(const __half2*)(qb + D + 2));

    float4 r;
    r.x = q01.x + q01.y + q23.x + q23.y;
    r.y = fmaf(q01.x, q01.x, fmaf(q01.y, q01.y, fmaf(q23.x, q23.x, q23.y * q23.y)));
    r.z = k01.x + k01.y + k23.x + k23.y;
    r.w = fmaf(k01.x, k01.x, fmaf(k01.y, k01.y, fmaf(k23.x, k23.x, k23.y * k23.y)));
    r = block_reduce_sum4(r);

    const int d0 = 4 * tid, head = d0 >> 6, dh0 = d0 & 63;
    const size_t obase = ((size_t)(b * H + head) * L + l) * DH + dh0;

    // q segment (scaled into exp2 domain)
    {
        const float mu = r.x * (1.0f / D);
        const float rs = rsqrtf(r.y * (1.0f / D) - mu * mu + EPS);
        const float4 wv = *(const float4*)(q_ln_w + 4 * tid);
        float y[4] = {(q01.x - mu) * rs * wv.x, (q01.y - mu) * rs * wv.y,
                      (q23.x - mu) * rs * wv.z, (q23.y - mu) * rs * wv.w};
        float out[4];
        #pragma unroll
        for (int c = 0; c < 4; c++) {
            float p = __shfl_xor_sync(0xffffffffu, y[c], 8);
            out[c] = fmaf(sgn * p, sn[c], y[c] * cs[c]);
        }
        const float QS = 0.125f * LOG2E;
        __half* dp = g_qh + obase;
        *(__half2*)(dp)     = __floats2half2_rn(out[0] * QS, out[1] * QS);
        *(__half2*)(dp + 2) = __floats2half2_rn(out[2] * QS, out[3] * QS);
    }
    // k segment
    {
        const float mu = r.z * (1.0f / D);
        const float rs = rsqrtf(r.w * (1.0f / D) - mu * mu + EPS);
        const float4 wv = *(const float4*)(k_ln_w + 4 * tid);
        float y[4] = {(k01.x - mu) * rs * wv.x, (k01.y - mu) * rs * wv.y,
                      (k23.x - mu) * rs * wv.z, (k23.y - mu) * rs * wv.w};
        float out[4];
        #pragma unroll
        for (int c = 0; c < 4; c++) {
            float p = __shfl_xor_sync(0xffffffffu, y[c], 8);
            out[c] = fmaf(sgn * p, sn[c], y[c] * cs[c]);
        }
        __half* dp = g_kh + obase;
        *(__half2*)(dp)     = __floats2half2_rn(out[0], out[1]);
        *(__half2*)(dp + 2) = __floats2half2_rn(out[2], out[3]);
    }
    // v copy
    {
        const __half* base = g_qkv_h + (size_t)t * (3 * D) + 2 * D + 4 * tid;
        *(uint2*)(g_vh + obase) = *(const uint2*)base;
    }
}

// ---------------------------------------------------------------------------
// Kernel 4: fp16 flash attention; exp2-domain softmax; 4-stage KV ring
// with 2 tiles in flight (wait_group 2).
// ---------------------------------------------------------------------------
constexpr int AST = 72;
constexpr int AKB = 64 * AST;
constexpr int NSTG = 4;
constexpr int ATTN_SMEM = (2 * NSTG * AKB + 8 * 16 * AST) * 2;   // 92160 B
constexpr int NKT = L / 64;

__global__ void __launch_bounds__(256) attn_f16(__half* __restrict__ ctx)
{
    extern __shared__ __half hsm[];
    const uint32_t ks0 = smem_u32(hsm);
    const uint32_t vs0 = smem_u32(hsm + NSTG * AKB);
    __half* Qstage = hsm + 2 * NSTG * AKB + (threadIdx.x >> 5) * 16 * AST;
    const uint32_t qs0 = smem_u32(Qstage);

    const int tid  = threadIdx.x;
    const int lane = tid & 31;
    const int g    = lane >> 2;
    const int tg   = lane & 3;
    const int w    = tid >> 5;
    const int bh   = blockIdx.y;
    const int bb   = bh / H;
    const int hh   = bh % H;
    const int q0   = blockIdx.x * 128;

    const __half* Kg0 = g_kh + (size_t)bh * L * DH;
    const __half* Vg0 = g_vh + (size_t)bh * L * DH;

    auto stage_kv = [&](int slot, int kt) {
        const __half* Kg = Kg0 + (size_t)kt * 64 * DH;
        const __half* Vg = Vg0 + (size_t)kt * 64 * DH;
        const uint32_t kd = ks0 + slot * AKB * 2;
        const uint32_t vd = vs0 + slot * AKB * 2;
        #pragma unroll
        for (int r = 0; r < 2; r++) {
            int idx = tid + r * 256;
            int row = idx >> 3, col = (idx & 7) * 8;
            cp_async16(kd + (row * AST + col) * 2, Kg + row * DH + col);
            cp_async16(vd + (row * AST + col) * 2, Vg + row * DH + col);
        }
    };

    stage_kv(0, 0); CP_COMMIT();
    stage_kv(1, 1); CP_COMMIT();
    stage_kv(2, 2); CP_COMMIT();

    uint32_t qa[4][4];
    {
        const __half* Qg = g_qh + ((size_t)bh * L + q0 + w * 16) * DH;
        #pragma unroll
        for (int r = 0; r < 4; r++) {
            int idx = lane + r * 32;
            int row = idx >> 3, col = (idx & 7) * 8;
            *(float4*)&Qstage[row * AST + col] = *(const float4*)(Qg + row * DH + col);
        }
        __syncwarp();
        const uint32_t qaddr = qs0 + ((lane & 15) * AST + (lane >> 4) * 8) * 2;
        #pragma unroll
        for (int ks = 0; ks < 4; ks++)
            LDMX4(qa[ks][0], qa[ks][1], qa[ks][2], qa[ks][3], qaddr + ks * 32);
    }

    float m0 = -1e30f, m1 = -1e30f, l0 = 0.0f, l1 = 0.0f;
    float o[8][4];
    #pragma unroll
    for (int nt = 0; nt < 8; nt++)
        #pragma unroll
        for (int i = 0; i < 4; i++) o[nt][i] = 0.0f;

    const uint32_t k_lane = (((lane & 7) + ((lane >> 4) << 3)) * AST +
                             ((lane >> 3) & 1) * 8) * 2;
    const uint32_t v_lane = (((lane & 7) + (((lane >> 3) & 1) << 3)) * AST +
                             ((lane >> 4) << 3)) * 2;

    for (int kt = 0; kt < NKT; kt++) {
        CP_WAIT2();                 // tiles <= kt resident; 2 tiles in flight
        __syncthreads();
        if (kt + 3 < NKT) stage_kv((kt + 3) % NSTG, kt + 3);
        CP_COMMIT();

        const uint32_t ksb = ks0 + (kt % NSTG) * AKB * 2;
        const uint32_t vsb = vs0 + (kt % NSTG) * AKB * 2;

        // S = Q' K^T (exp2 domain)
        float s[8][4];
        #pragma unroll
        for (int nt = 0; nt < 8; nt++)
            #pragma unroll
            for (int i = 0; i < 4; i++) s[nt][i] = 0.0f;

        #pragma unroll
        for (int ks = 0; ks < 4; ks++) {
            uint32_t bk[8][2];
            #pragma unroll
            for (int p = 0; p < 4; p++)
                LDMX4(bk[2*p][0], bk[2*p][1], bk[2*p+1][0], bk[2*p+1][1],
                      ksb + p * 16 * AST * 2 + ks * 32 + k_lane);
            #pragma unroll
            for (int nt = 0; nt < 8; nt++) mma16(s[nt], qa[ks], bk[nt]);
        }

        // online softmax (exp2 domain)
        float mx0 = -1e30f, mx1 = -1e30f;
        #pragma unroll
        for (int nt = 0; nt < 8; nt++) {
            mx0 = fmaxf(mx0, fmaxf(s[nt][0], s[nt][1]));
            mx1 = fmaxf(mx1, fmaxf(s[nt][2], s[nt][3]));
        }
        mx0 = fmaxf(mx0, __shfl_xor_sync(0xffffffffu, mx0, 1));
        mx0 = fmaxf(mx0, __shfl_xor_sync(0xffffffffu, mx0, 2));
        mx1 = fmaxf(mx1, __shfl_xor_sync(0xffffffffu, mx1, 1));
        mx1 = fmaxf(mx1, __shfl_xor_sync(0xffffffffu, mx1, 2));
        const float nm0 = fmaxf(m0, mx0);
        const float nm1 = fmaxf(m1, mx1);

        float sum0 = 0.0f, sum1 = 0.0f;
        uint32_t ph[8][2];
        #pragma unroll
        for (int nt = 0; nt < 8; nt++) {
            float e0 = ex2f(s[nt][0] - nm0);
            float e1 = ex2f(s[nt][1] - nm0);
            float e2 = ex2f(s[nt][2] - nm1);
            float e3 = ex2f(s[nt][3] - nm1);
            sum0 += e0 + e1;
            sum1 += e2 + e3;
            ph[nt][0] = packh2(e0, e1);
            ph[nt][1] = packh2(e2, e3);
        }
        sum0 += __shfl_xor_sync(0xffffffffu, sum0, 1);
        sum0 += __shfl_xor_sync(0xffffffffu, sum0, 2);
        sum1 += __shfl_xor_sync(0xffffffffu, sum1, 1);
        sum1 += __shfl_xor_sync(0xffffffffu, sum1, 2);

        const float al0 = ex2f(m0 - nm0);
        const float al1 = ex2f(m1 - nm1);
        l0 = l0 * al0 + sum0;  m0 = nm0;
        l1 = l1 * al1 + sum1;  m1 = nm1;

        #pragma unroll
        for (int nt = 0; nt < 8; nt++) {
            o[nt][0] *= al0; o[nt][1] *= al0;
            o[nt][2] *= al1; o[nt][3] *= al1;
        }

        #pragma unroll
        for (int ks = 0; ks < 4; ks++) {
            uint32_t a[4] = {ph[2*ks][0], ph[2*ks][1], ph[2*ks+1][0], ph[2*ks+1][1]};
            #pragma unroll
            for (int p = 0; p < 4; p++) {
                uint32_t b0, b1, b2, b3;
                LDMX4T(b0, b1, b2, b3, vsb + (ks * 16) * AST * 2 + p * 32 + v_lane);
                uint32_t bA[2] = {b0, b1}, bB[2] = {b2, b3};
                mma16(o[2*p],     a, bA);
                mma16(o[2*p + 1], a, bB);
            }
        }
    }

    const float inv0 = 1.0f / l0;
    const float inv1 = 1.0f / l1;
    const int row0 = q0 + w * 16 + g;
    const int row1 = row0 + 8;
    #pragma unroll
    for (int nt = 0; nt < 8; nt++) {
        const int col = hh * DH + nt * 8 + 2 * tg;
        *(__half2*)(ctx + (size_t)(bb * L + row0) * D + col) =
            __floats2half2_rn(o[nt][0] * inv0, o[nt][1] * inv0);
        *(__half2*)(ctx + (size_t)(bb * L + row1) * D + col) =
            __floats2half2_rn(o[nt][2] * inv1, o[nt][3] * inv1);
    }
}

// Launch
extern "C" void kernel_launch(void* const* d_in, const int* in_sizes, int n_in,
                              void* d_out, int out_size)
{
    const float* x      = (const float*)d_in[0];
    const float* ln_w   = (const float*)d_in[1];
    const float* ln_b   = (const float*)d_in[2];
    const float* w_qkv  = (const float*)d_in[3];
    const float* q_ln_w = (const float*)d_in[4];
    const float* k_ln_w = (const float*)d_in[5];
    const float* w_out  = (const float*)d_in[6];
    float* out = (float*)d_out;

    __half *hh, *wq, *wo, *qkv, *ctx;
    cudaGetSymbolAddress((void**)&hh,  g_h_h);
    cudaGetSymbolAddress((void**)&wq,  g_wqkv_h);
    cudaGetSymbolAddress((void**)&wo,  g_wout_h);
    cudaGetSymbolAddress((void**)&qkv, g_qkv_h);
    cudaGetSymbolAddress((void**)&ctx, g_ctx_h);

    cudaFuncSetAttribute(gemm_nt_f16<__half>, cudaFuncAttributeMaxDynamicSharedMemorySize, GEMM_SMEM);
    cudaFuncSetAttribute(gemm_nt_f16<float>,  cudaFuncAttributeMaxDynamicSharedMemorySize, GEMM_SMEM);
    cudaFuncSetAttribute(attn_f16, cudaFuncAttributeMaxDynamicSharedMemorySize, ATTN_SMEM);

    ln_prep_kernel<<<BL + 4096 + 256, 256>>>(x, ln_w, ln_b, w_qkv, w_out);
    {
        dim3 grid(3 * D / 128, BL / 128);
        gemm_nt_f16<__half><<<grid, 256, GEMM_SMEM>>>(hh, wq, qkv, BL, 3 * D, D);
    }
    qk_rope_kernel<<<BL, 256>>>(q_ln_w, k_ln_w);
    {
        dim3 grid(L / 128, B * H);
        attn_f16<<<grid, 256, ATTN_SMEM>>>(ctx);
    }
    {
        dim3 grid(D / 128, BL / 128);
        gemm_nt_f16<float><<<grid, 256, GEMM_SMEM>>>(ctx, wo, out, BL, D, D);
    }
}

// round 13
// speedup vs baseline: 2.4158x; 1.0055x over previous
#include <cuda_runtime.h>
#include <cuda_fp16.h>
#include <math.h>
#include <stdint.h>

constexpr int B  = 2;
constexpr int L  = 2048;
constexpr int D  = 1024;
constexpr int H  = 16;
constexpr int DH = 64;
constexpr int BL = B * L;
constexpr float EPS = 1e-5f;
constexpr float LOG_ROPE_BASE = 9.210340371976184f;
constexpr float LOG2E = 1.4426950408889634f;

// Scratch
__device__ __half g_h_h[BL * D];
__device__ __half g_wqkv_h[3 * D * D];
__device__ __half g_wout_h[D * D];
__device__ __half g_qkv_h[BL * 3 * D];
__device__ __half g_qh[BL * D];     // pre-scaled by (1/8)*log2(e)
__device__ __half g_kh[BL * D];
__device__ __half g_ctx_h[BL * D];
__device__ float2 g_rope[L * 32];

// Helpers
__device__ __forceinline__ uint32_t smem_u32(const void* p) {
    return (uint32_t)__cvta_generic_to_shared(p);
}
__device__ __forceinline__ void cp_async16(uint32_t dst, const void* src) {
    asm volatile("cp.async.cg.shared.global [%0], [%1], 16;" :: "r"(dst), "l"(src));
}
#define CP_COMMIT() asm volatile("cp.async.commit_group;")
#define CP_WAIT1()  asm volatile("cp.async.wait_group 1;")
#define CP_WAIT2()  asm volatile("cp.async.wait_group 2;")
#define LDMX4(r0,r1,r2,r3,addr) \
    asm volatile("ldmatrix.sync.aligned.m8n8.x4.shared.b16 {%0,%1,%2,%3},[%4];" \
                 : "=r"(r0),"=r"(r1),"=r"(r2),"=r"(r3) : "r"(addr))
#define LDMX4T(r0,r1,r2,r3,addr) \
    asm volatile("ldmatrix.sync.aligned.m8n8.x4.trans.shared.b16 {%0,%1,%2,%3},[%4];" \
                 : "=r"(r0),"=r"(r1),"=r"(r2),"=r"(r3) : "r"(addr))

__device__ __forceinline__ void mma16(float* c, const uint32_t* a, const uint32_t* b) {
    asm volatile(
        "mma.sync.aligned.m16n8k16.row.col.f32.f16.f16.f32 "
        "{%0,%1,%2,%3},{%4,%5,%6,%7},{%8,%9},{%0,%1,%2,%3};"
        : "+f"(c[0]), "+f"(c[1]), "+f"(c[2]), "+f"(c[3])
        : "r"(a[0]), "r"(a[1]), "r"(a[2]), "r"(a[3]), "r"(b[0]), "r"(b[1]));
}

__device__ __forceinline__ uint32_t packh2(float a, float b) {
    __half2 h = __floats2half2_rn(a, b);
    return *(uint32_t*)&h;
}
__device__ __forceinline__ float ex2f(float x) {
    float r; asm("ex2.approx.ftz.f32 %0, %1;" : "=f"(r) : "f"(x)); return r;
}

// Fused 2-value block reduction (one barrier pair)
__device__ __forceinline__ float2 block_reduce_sum2(float2 v) {
    __shared__ float2 sb2[8];
    const int tid = threadIdx.x;
    #pragma unroll
    for (int o = 16; o > 0; o >>= 1) {
        v.x += __shfl_xor_sync(0xffffffffu, v.x, o);
        v.y += __shfl_xor_sync(0xffffffffu, v.y, o);
    }
    if ((tid & 31) == 0) sb2[tid >> 5] = v;
    __syncthreads();
    if (tid < 8) {
        float2 w = sb2[tid];
        #pragma unroll
        for (int o = 4; o > 0; o >>= 1) {
            w.x += __shfl_xor_sync(0xffu, w.x, o);
            w.y += __shfl_xor_sync(0xffu, w.y, o);
        }
        if (tid == 0) sb2[0] = w;
    }
    __syncthreads();
    return sb2[0];
}

__device__ __forceinline__ float4 block_reduce_sum4(float4 v) {
    __shared__ float4 sb[8];
    const int tid = threadIdx.x;
    #pragma unroll
    for (int o = 16; o > 0; o >>= 1) {
        v.x += __shfl_xor_sync(0xffffffffu, v.x, o);
        v.y += __shfl_xor_sync(0xffffffffu, v.y, o);
        v.z += __shfl_xor_sync(0xffffffffu, v.z, o);
        v.w += __shfl_xor_sync(0xffffffffu, v.w, o);
    }
    if ((tid & 31) == 0) sb[tid >> 5] = v;
    __syncthreads();
    if (tid < 8) {
        float4 w = sb[tid];
        #pragma unroll
        for (int o = 4; o > 0; o >>= 1) {
            w.x += __shfl_xor_sync(0xffu, w.x, o);
            w.y += __shfl_xor_sync(0xffu, w.y, o);
            w.z += __shfl_xor_sync(0xffu, w.z, o);
            w.w += __shfl_xor_sync(0xffu, w.w, o);
        }
        if (tid == 0) sb[0] = w;
    }
    __syncthreads();
    return sb[0];
}

// ---------------------------------------------------------------------------
// Kernel 1 (merged): LN + weight fp16 conversion + rope table
// ---------------------------------------------------------------------------
__global__ void __launch_bounds__(256) ln_prep_kernel(
    const float* __restrict__ x, const float* __restrict__ w,
    const float* __restrict__ bias,
    const float* __restrict__ wq, const float* __restrict__ wo)
{
    const int bid = blockIdx.x;
    const int tid = threadIdx.x;
    if (bid < BL) {
        const int t = bid;
        const float4 xv = *(const float4*)(x + (size_t)t * D + 4 * tid);
        float2 r;
        r.x = xv.x + xv.y + xv.z + xv.w;
        r.y = fmaf(xv.x, xv.x, fmaf(xv.y, xv.y, fmaf(xv.z, xv.z, xv.w * xv.w)));
        r = block_reduce_sum2(r);
        const float mu = r.x * (1.0f / D);
        const float rs = rsqrtf(r.y * (1.0f / D) - mu * mu + EPS);
        const float4 wv = *(const float4*)(w    + 4 * tid);
        const float4 bv = *(const float4*)(bias + 4 * tid);
        __half* dst = g_h_h + (size_t)t * D + 4 * tid;
        *(__half2*)(dst)     = __floats2half2_rn((xv.x - mu) * rs * wv.x + bv.x,
                                                 (xv.y - mu) * rs * wv.y + bv.y);
        *(__half2*)(dst + 2) = __floats2half2_rn((xv.z - mu) * rs * wv.z + bv.z,
                                                 (xv.w - mu) * rs * wv.w + bv.w);
    } else if (bid < BL + 4096) {
        const size_t i4 = ((size_t)(bid - BL) * 256 + tid) * 4;
        const size_t n1 = (size_t)3 * D * D;
        if (i4 < n1) {
            float4 v = *(const float4*)(wq + i4);
            *(__half2*)(g_wqkv_h + i4)     = __floats2half2_rn(v.x, v.y);
            *(__half2*)(g_wqkv_h + i4 + 2) = __floats2half2_rn(v.z, v.w);
        } else {
            size_t j = i4 - n1;
            float4 v = *(const float4*)(wo + j);
            *(__half2*)(g_wout_h + j)     = __floats2half2_rn(v.x, v.y);
            *(__half2*)(g_wout_h + j + 2) = __floats2half2_rn(v.z, v.w);
        }
    } else {
        const int idx = (bid - BL - 4096) * 256 + tid;
        const int l = idx >> 5;
        const int i = idx & 31;
        float inv_freq = expf(-(float)(2 * i) * (1.0f / 64.0f) * LOG_ROPE_BASE);
        float sn, cs;
        sincosf((float)l * inv_freq, &sn, &cs);
        g_rope[idx] = make_float2(cs, sn);
    }
}

// ---------------------------------------------------------------------------
// Kernel 2/5: fp16 GEMM-NT, K-chunk 64, 3-stage cp.async ring.
// ---------------------------------------------------------------------------
constexpr int GST  = 72;
constexpr int GBUF = 128 * GST * 2;
constexpr int GEMM_SMEM = 6 * GBUF;

__device__ __forceinline__ void store2(float* p, float a, float b) {
    *(float2*)p = make_float2(a, b);
}
__device__ __forceinline__ void store2(__half* p, float a, float b) {
    *(__half2*)p = __floats2half2_rn(a, b);
}

template <typename TOut>
__global__ void __launch_bounds__(256) gemm_nt_f16(
    const __half* __restrict__ A, const __half* __restrict__ Bm,
    TOut* __restrict__ C, int M, int N, int K)
{
    extern __shared__ __half gsm[];
    const uint32_t as0 = smem_u32(gsm);
    const uint32_t bs0 = smem_u32(gsm + 3 * 128 * GST);

    const int tid  = threadIdx.x;
    const int lane = tid & 31;
    const int g    = lane >> 2;
    const int tg   = lane & 3;
    const int wid  = tid >> 5;
    const int wm   = wid >> 2;
    const int wn   = wid & 3;
    const int m0   = blockIdx.y * 128;
    const int n0   = blockIdx.x * 128;

    float acc[4][4][4];
    #pragma unroll
    for (int mt = 0; mt < 4; mt++)
        #pragma unroll
        for (int nt = 0; nt < 4; nt++)
            #pragma unroll
            for (int i = 0; i < 4; i++) acc[mt][nt][i] = 0.0f;

    auto stage = [&](int s, int k0) {
        #pragma unroll
        for (int r = 0; r < 4; r++) {
            int qid = tid + r * 256;
            int row = qid >> 3;
            int cq  = (qid & 7) * 8;
            cp_async16(as0 + s * GBUF + (row * GST + cq) * 2,
                       A + (size_t)(m0 + row) * K + k0 + cq);
            cp_async16(bs0 + s * GBUF + (row * GST + cq) * 2,
                       Bm + (size_t)(n0 + row) * K + k0 + cq);
        }
    };
    stage(0, 0);  CP_COMMIT();
    stage(1, 64); CP_COMMIT();

    const uint32_t a_lane = ((lane & 15) * GST + (lane >> 4) * 8) * 2;
    const uint32_t b_lane = ((((lane >> 4) << 3) + (lane & 7)) * GST +
                             ((lane >> 3) & 1) * 8) * 2;

    const int NIT = K / 64;
    for (int kt = 0; kt < NIT; kt++) {
        CP_WAIT1();
        __syncthreads();
        if (kt + 2 < NIT) stage((kt + 2) % 3, (kt + 2) * 64);
        CP_COMMIT();

        const uint32_t ab = as0 + (kt % 3) * GBUF + (wm * 64) * GST * 2 + a_lane;
        const uint32_t bb = bs0 + (kt % 3) * GBUF + (wn * 32) * GST * 2 + b_lane;

        #pragma unroll
        for (int kk = 0; kk < 4; kk++) {
            uint32_t bf[4][2];
            #pragma unroll
            for (int p = 0; p < 2; p++)
                LDMX4(bf[2*p][0], bf[2*p][1], bf[2*p+1][0], bf[2*p+1][1],
                      bb + p * 16 * GST * 2 + kk * 32);
            #pragma unroll
            for (int mt = 0; mt < 4; mt++) {
                uint32_t a[4];
                LDMX4(a[0], a[1], a[2], a[3], ab + mt * 16 * GST * 2 + kk * 32);
                #pragma unroll
                for (int nt = 0; nt < 4; nt++) mma16(acc[mt][nt], a, bf[nt]);
            }
        }
    }

    #pragma unroll
    for (int mt = 0; mt < 4; mt++) {
        const int m = m0 + wm * 64 + mt * 16 + g;
        #pragma unroll
        for (int nt = 0; nt < 4; nt++) {
            const int n = n0 + wn * 32 + nt * 8 + 2 * tg;
            store2(C + (size_t)m * N + n,       acc[mt][nt][0], acc[mt][nt][1]);
            store2(C + (size_t)(m + 8) * N + n, acc[mt][nt][2], acc[mt][nt][3]);
        }
    }
}

// ---------------------------------------------------------------------------
// Kernel 3: q/k LN + RoPE (shfl rotation). Q scaled by (1/8)*log2(e).
// V is NOT copied: attention reads it in place from g_qkv_h.
// ---------------------------------------------------------------------------
__global__ void __launch_bounds__(256) qk_rope_kernel(
    const float* __restrict__ q_ln_w, const float* __restrict__ k_ln_w)
{
    const int t = blockIdx.x, tid = threadIdx.x;
    const int b = t / L, l = t % L;

    const int i0 = (4 * tid) & 31;
    float4 rc0 = *(const float4*)(g_rope + l * 32 + i0);
    float4 rc1 = *(const float4*)(g_rope + l * 32 + i0 + 2);
    const float cs[4] = {rc0.x, rc0.z, rc1.x, rc1.z};
    const float sn[4] = {rc0.y, rc0.w, rc1.y, rc1.w};
    const float sgn = (tid & 8) ? 1.0f : -1.0f;

    const __half* qb = g_qkv_h + (size_t)t * (3 * D) + 4 * tid;
    float2 q01 = __half22float2(*(const __half2*)(qb));
    float2 q23 = __half22float2(*(const __half2*)(qb + 2));
    float2 k01 = __half22float2(*(const __half2*)(qb + D));
    float2 k23 = __half22float2(*(const __half2*)(qb + D + 2));

    float4 r;
    r.x = q01.x + q01.y + q23.x + q23.y;
    r.y = fmaf(q01.x, q01.x, fmaf(q01.y, q01.y, fmaf(q23.x, q23.x, q23.y * q23.y)));
    r.z = k01.x + k01.y + k23.x + k23.y;
    r.w = fmaf(k01.x, k01.x, fmaf(k01.y, k01.y, fmaf(k23.x, k23.x, k23.y * k23.y)));
    r = block_reduce_sum4(r);

    const int d0 = 4 * tid, head = d0 >> 6, dh0 = d0 & 63;
    const size_t obase = ((size_t)(b * H + head) * L + l) * DH + dh0;

    // q segment (scaled into exp2 domain)
    {
        const float mu = r.x * (1.0f / D);
        const float rs = rsqrtf(r.y * (1.0f / D) - mu * mu + EPS);
        const float4 wv = *(const float4*)(q_ln_w + 4 * tid);
        float y[4] = {(q01.x - mu) * rs * wv.x, (q01.y - mu) * rs * wv.y,
                      (q23.x - mu) * rs * wv.z, (q23.y - mu) * rs * wv.w};
        float out[4];
        #pragma unroll
        for (int c = 0; c < 4; c++) {
            float p = __shfl_xor_sync(0xffffffffu, y[c], 8);
            out[c] = fmaf(sgn * p, sn[c], y[c] * cs[c]);
        }
        const float QS = 0.125f * LOG2E;
        __half* dp = g_qh + obase;
        *(__half2*)(dp)     = __floats2half2_rn(out[0] * QS, out[1] * QS);
        *(__half2*)(dp + 2) = __floats2half2_rn(out[2] * QS, out[3] * QS);
    }
    // k segment
    {
        const float mu = r.z * (1.0f / D);
        const float rs = rsqrtf(r.w * (1.0f / D) - mu * mu + EPS);
        const float4 wv = *(const float4*)(k_ln_w + 4 * tid);
        float y[4] = {(k01.x - mu) * rs * wv.x, (k01.y - mu) * rs * wv.y,
                      (k23.x - mu) * rs * wv.z, (k23.y - mu) * rs * wv.w};
        float out[4];
        #pragma unroll
        for (int c = 0; c < 4; c++) {
            float p = __shfl_xor_sync(0xffffffffu, y[c], 8);
            out[c] = fmaf(sgn * p, sn[c], y[c] * cs[c]);
        }
        __half* dp = g_kh + obase;
        *(__half2*)(dp)     = __floats2half2_rn(out[0], out[1]);
        *(__half2*)(dp + 2) = __floats2half2_rn(out[2], out[3]);
    }
}

// ---------------------------------------------------------------------------
// Kernel 4: fp16 flash attention; exp2-domain softmax; 4-stage KV ring
// (2 tiles in flight); V read in place from g_qkv_h; PV loads batched.
// ---------------------------------------------------------------------------
constexpr int AST = 72;
constexpr int AKB = 64 * AST;
constexpr int NSTG = 4;
constexpr int ATTN_SMEM = (2 * NSTG * AKB + 8 * 16 * AST) * 2;   // 92160 B
constexpr int NKT = L / 64;

__global__ void __launch_bounds__(256) attn_f16(__half* __restrict__ ctx)
{
    extern __shared__ __half hsm[];
    const uint32_t ks0 = smem_u32(hsm);
    const uint32_t vs0 = smem_u32(hsm + NSTG * AKB);
    __half* Qstage = hsm + 2 * NSTG * AKB + (threadIdx.x >> 5) * 16 * AST;
    const uint32_t qs0 = smem_u32(Qstage);

    const int tid  = threadIdx.x;
    const int lane = tid & 31;
    const int g    = lane >> 2;
    const int tg   = lane & 3;
    const int w    = tid >> 5;
    const int bh   = blockIdx.y;
    const int bb   = bh / H;
    const int hh   = bh % H;
    const int q0   = blockIdx.x * 128;

    const __half* Kg0 = g_kh + (size_t)bh * L * DH;
    const __half* Vg0 = g_qkv_h + (size_t)(bb * L) * (3 * D) + 2 * D + hh * DH;

    auto stage_kv = [&](int slot, int kt) {
        const __half* Kg = Kg0 + (size_t)kt * 64 * DH;
        const __half* Vg = Vg0 + (size_t)(kt * 64) * (3 * D);
        const uint32_t kd = ks0 + slot * AKB * 2;
        const uint32_t vd = vs0 + slot * AKB * 2;
        #pragma unroll
        for (int r = 0; r < 2; r++) {
            int idx = tid + r * 256;
            int row = idx >> 3, col = (idx & 7) * 8;
            cp_async16(kd + (row * AST + col) * 2, Kg + row * DH + col);
            cp_async16(vd + (row * AST + col) * 2, Vg + (size_t)row * (3 * D) + col);
        }
    };

    stage_kv(0, 0); CP_COMMIT();
    stage_kv(1, 1); CP_COMMIT();
    stage_kv(2, 2); CP_COMMIT();

    uint32_t qa[4][4];
    {
        const __half* Qg = g_qh + ((size_t)bh * L + q0 + w * 16) * DH;
        #pragma unroll
        for (int r = 0; r < 4; r++) {
            int idx = lane + r * 32;
            int row = idx >> 3, col = (idx & 7) * 8;
            *(float4*)&Qstage[row * AST + col] = *(const float4*)(Qg + row * DH + col);
        }
        __syncwarp();
        const uint32_t qaddr = qs0 + ((lane & 15) * AST + (lane >> 4) * 8) * 2;
        #pragma unroll
        for (int ks = 0; ks < 4; ks++)
            LDMX4(qa[ks][0], qa[ks][1], qa[ks][2], qa[ks][3], qaddr + ks * 32);
    }

    float m0 = -1e30f, m1 = -1e30f, l0 = 0.0f, l1 = 0.0f;
    float o[8][4];
    #pragma unroll
    for (int nt = 0; nt < 8; nt++)
        #pragma unroll
        for (int i = 0; i < 4; i++) o[nt][i] = 0.0f;

    const uint32_t k_lane = (((lane & 7) + ((lane >> 4) << 3)) * AST +
                             ((lane >> 3) & 1) * 8) * 2;
    const uint32_t v_lane = (((lane & 7) + (((lane >> 3) & 1) << 3)) * AST +
                             ((lane >> 4) << 3)) * 2;

    for (int kt = 0; kt < NKT; kt++) {
        CP_WAIT2();
        __syncthreads();
        if (kt + 3 < NKT) stage_kv((kt + 3) % NSTG, kt + 3);
        CP_COMMIT();

        const uint32_t ksb = ks0 + (kt % NSTG) * AKB * 2;
        const uint32_t vsb = vs0 + (kt % NSTG) * AKB * 2;

        // S = Q' K^T (exp2 domain)
        float s[8][4];
        #pragma unroll
        for (int nt = 0; nt < 8; nt++)
            #pragma unroll
            for (int i = 0; i < 4; i++) s[nt][i] = 0.0f;

        #pragma unroll
        for (int ks = 0; ks < 4; ks++) {
            uint32_t bk[8][2];
            #pragma unroll
            for (int p = 0; p < 4; p++)
                LDMX4(bk[2*p][0], bk[2*p][1], bk[2*p+1][0], bk[2*p+1][1],
                      ksb + p * 16 * AST * 2 + ks * 32 + k_lane);
            #pragma unroll
            for (int nt = 0; nt < 8; nt++) mma16(s[nt], qa[ks], bk[nt]);
        }

        // online softmax (exp2 domain)
        float mx0 = -1e30f, mx1 = -1e30f;
        #pragma unroll
        for (int nt = 0; nt < 8; nt++) {
            mx0 = fmaxf(mx0, fmaxf(s[nt][0], s[nt][1]));
            mx1 = fmaxf(mx1, fmaxf(s[nt][2], s[nt][3]));
        }
        mx0 = fmaxf(mx0, __shfl_xor_sync(0xffffffffu, mx0, 1));
        mx0 = fmaxf(mx0, __shfl_xor_sync(0xffffffffu, mx0, 2));
        mx1 = fmaxf(mx1, __shfl_xor_sync(0xffffffffu, mx1, 1));
        mx1 = fmaxf(mx1, __shfl_xor_sync(0xffffffffu, mx1, 2));
        const float nm0 = fmaxf(m0, mx0);
        const float nm1 = fmaxf(m1, mx1);

        float sum0 = 0.0f, sum1 = 0.0f;
        uint32_t ph[8][2];
        #pragma unroll
        for (int nt = 0; nt < 8; nt++) {
            float e0 = ex2f(s[nt][0] - nm0);
            float e1 = ex2f(s[nt][1] - nm0);
            float e2 = ex2f(s[nt][2] - nm1);
            float e3 = ex2f(s[nt][3] - nm1);
            sum0 += e0 + e1;
            sum1 += e2 + e3;
            ph[nt][0] = packh2(e0, e1);
            ph[nt][1] = packh2(e2, e3);
        }
        sum0 += __shfl_xor_sync(0xffffffffu, sum0, 1);
        sum0 += __shfl_xor_sync(0xffffffffu, sum0, 2);
        sum1 += __shfl_xor_sync(0xffffffffu, sum1, 1);
        sum1 += __shfl_xor_sync(0xffffffffu, sum1, 2);

        const float al0 = ex2f(m0 - nm0);
        const float al1 = ex2f(m1 - nm1);
        l0 = l0 * al0 + sum0;  m0 = nm0;
        l1 = l1 * al1 + sum1;  m1 = nm1;

        #pragma unroll
        for (int nt = 0; nt < 8; nt++) {
            o[nt][0] *= al0; o[nt][1] *= al0;
            o[nt][2] *= al1; o[nt][3] *= al1;
        }

        // O += P @ V (all V frags loaded before MMAs for dependency distance)
        #pragma unroll
        for (int ks = 0; ks < 4; ks++) {
            uint32_t a[4] = {ph[2*ks][0], ph[2*ks][1], ph[2*ks+1][0], ph[2*ks+1][1]};
            uint32_t bv[8][2];
            #pragma unroll
            for (int p = 0; p < 4; p++)
                LDMX4T(bv[2*p][0], bv[2*p][1], bv[2*p+1][0], bv[2*p+1][1],
                       vsb + (ks * 16) * AST * 2 + p * 32 + v_lane);
            #pragma unroll
            for (int p = 0; p < 8; p++) mma16(o[p], a, bv[p]);
        }
    }

    const float inv0 = 1.0f / l0;
    const float inv1 = 1.0f / l1;
    const int row0 = q0 + w * 16 + g;
    const int row1 = row0 + 8;
    #pragma unroll
    for (int nt = 0; nt < 8; nt++) {
        const int col = hh * DH + nt * 8 + 2 * tg;
        *(__half2*)(ctx + (size_t)(bb * L + row0) * D + col) =
            __floats2half2_rn(o[nt][0] * inv0, o[nt][1] * inv0);
        *(__half2*)(ctx + (size_t)(bb * L + row1) * D + col) =
            __floats2half2_rn(o[nt][2] * inv1, o[nt][3] * inv1);
    }
}

// Launch
extern "C" void kernel_launch(void* const* d_in, const int* in_sizes, int n_in,
                              void* d_out, int out_size)
{
    const float* x      = (const float*)d_in[0];
    const float* ln_w   = (const float*)d_in[1];
    const float* ln_b   = (const float*)d_in[2];
    const float* w_qkv  = (const float*)d_in[3];
    const float* q_ln_w = (const float*)d_in[4];
    const float* k_ln_w = (const float*)d_in[5];
    const float* w_out  = (const float*)d_in[6];
    float* out = (float*)d_out;

    __half *hh, *wq, *wo, *qkv, *ctx;
    cudaGetSymbolAddress((void**)&hh,  g_h_h);
    cudaGetSymbolAddress((void**)&wq,  g_wqkv_h);
    cudaGetSymbolAddress((void**)&wo,  g_wout_h);
    cudaGetSymbolAddress((void**)&qkv, g_qkv_h);
    cudaGetSymbolAddress((void**)&ctx, g_ctx_h);

    cudaFuncSetAttribute(gemm_nt_f16<__half>, cudaFuncAttributeMaxDynamicSharedMemorySize, GEMM_SMEM);
    cudaFuncSetAttribute(gemm_nt_f16<float>,  cudaFuncAttributeMaxDynamicSharedMemorySize, GEMM_SMEM);
    cudaFuncSetAttribute(attn_f16, cudaFuncAttributeMaxDynamicSharedMemorySize, ATTN_SMEM);

    ln_prep_kernel<<<BL + 4096 + 256, 256>>>(x, ln_w, ln_b, w_qkv, w_out);
    {
        dim3 grid(3 * D / 128, BL / 128);
        gemm_nt_f16<__half><<<grid, 256, GEMM_SMEM>>>(hh, wq, qkv, BL, 3 * D, D);
    }
    qk_rope_kernel<<<BL, 256>>>(q_ln_w, k_ln_w);
    {
        dim3 grid(L / 128, B * H);
        attn_f16<<<grid, 256, ATTN_SMEM>>>(ctx);
    }
    {
        dim3 grid(D / 128, BL / 128);
        gemm_nt_f16<float><<<grid, 256, GEMM_SMEM>>>(ctx, wo, out, BL, D, D);
    }
}